// round 2
// baseline (speedup 1.0000x reference)
#include <cuda_runtime.h>

#define NN 100000
#define NH 20000
#define NE 1600000
#define DD 128
#define HH 512

// ---------------- scratch (device globals; no allocation allowed) ----------------
__device__ __align__(16) float g_deg_node[NN];
__device__ __align__(16) float g_deg_he[NH];
__device__ __align__(16) float g_hyper_acc[NH * DD];   // segment_sum(msg, dst)
__device__ __align__(16) float g_hyper_msg[NH * DD];   // ((acc*ch)@W1+b1)*ch
__device__ __align__(16) float g_node_acc[NN * DD];    // segment_sum(msg2, src)

// ---------------- packed fp32x2 helpers (Blackwell fma.rn.f32x2) ----------------
__device__ __forceinline__ unsigned long long f2_pack(float x, float y) {
    unsigned long long r;
    asm("mov.b64 %0, {%1, %2};" : "=l"(r) : "f"(x), "f"(y));
    return r;
}
__device__ __forceinline__ void f2_unpack(unsigned long long v, float& x, float& y) {
    asm("mov.b64 {%0, %1}, %2;" : "=f"(x), "=f"(y) : "l"(v));
}
__device__ __forceinline__ unsigned long long ffma2(unsigned long long a,
                                                    unsigned long long b,
                                                    unsigned long long c) {
    unsigned long long d;
    asm("fma.rn.f32x2 %0, %1, %2, %3;" : "=l"(d) : "l"(a), "l"(b), "l"(c));
    return d;
}

// 4 rows x 8 cols (4 f32x2 pairs) register tile, K=128.
// a_base: smem row base for this thread's 4 rows (stride a_stride, padded odd).
// w_base: smem weights as u64 pairs, row stride 64 pairs (=128 floats).
// cp0: this thread's first col-pair.
__device__ __forceinline__ void gemm_tile_k128(const float* __restrict__ a_base, int a_stride,
                                               const unsigned long long* __restrict__ w_base,
                                               int cp0, unsigned long long acc[4][4]) {
#pragma unroll 8
    for (int k = 0; k < 128; k++) {
        unsigned long long A[4];
#pragma unroll
        for (int i = 0; i < 4; i++) {
            float a = a_base[i * a_stride + k];
            A[i] = f2_pack(a, a);
        }
        unsigned long long w[4];
#pragma unroll
        for (int p = 0; p < 4; p++) w[p] = w_base[k * 64 + cp0 + p];
#pragma unroll
        for (int i = 0; i < 4; i++)
#pragma unroll
            for (int p = 0; p < 4; p++) acc[i][p] = ffma2(A[i], w[p], acc[i][p]);
    }
}

// ---------------- K0: zero scratch ----------------
__global__ void k_zero() {
    int idx = blockIdx.x * blockDim.x + threadIdx.x;
    int nthr = gridDim.x * blockDim.x;
    float4 z = make_float4(0.f, 0.f, 0.f, 0.f);
    for (int i = idx; i < NN * DD / 4; i += nthr) ((float4*)g_node_acc)[i] = z;
    for (int i = idx; i < NH * DD / 4; i += nthr) ((float4*)g_hyper_acc)[i] = z;
    for (int i = idx; i < NN; i += nthr) g_deg_node[i] = 0.f;
    for (int i = idx; i < NH; i += nthr) g_deg_he[i] = 0.f;
}

// ---------------- K1: degrees ----------------
__global__ void k_deg(const int* __restrict__ src, const int* __restrict__ dst) {
    int e = blockIdx.x * blockDim.x + threadIdx.x;
    if (e < NE) {
        atomicAdd(&g_deg_node[src[e]], 1.f);
        atomicAdd(&g_deg_he[dst[e]], 1.f);
    }
}

// ---------------- K2: scatter node -> hyper (msg = (h*cn)[src], segsum over dst) ----
__global__ void k_scatter1(const float* __restrict__ h, const int* __restrict__ src,
                           const int* __restrict__ dst) {
    int e = blockIdx.x * 8 + (threadIdx.x >> 5);
    if (e >= NE) return;
    int lane = threadIdx.x & 31;
    int s = __ldg(&src[e]);
    int d = __ldg(&dst[e]);
    float cn = rsqrtf(fmaxf(g_deg_node[s], 1.f));
    float4 v = __ldg(&((const float4*)h)[s * 32 + lane]);
    v.x *= cn; v.y *= cn; v.z *= cn; v.w *= cn;
    float* p = &g_hyper_acc[d * DD + lane * 4];
    asm volatile("red.global.add.v4.f32 [%0], {%1, %2, %3, %4};"
                 :: "l"(p), "f"(v.x), "f"(v.y), "f"(v.z), "f"(v.w) : "memory");
}

// ---------------- K3: hyper GEMM: g_hyper_msg = ((acc*ch)@W1 + b1)*ch ----------------
// = ch^2 * (acc@W1) + ch*b1
__global__ void k_gemm1(const float* __restrict__ W1, const float* __restrict__ b1) {
    extern __shared__ float sm[];
    float* sA = sm;                    // 64 x 129
    float* sW = sA + 64 * 129;         // 128 x 128
    float* sCh = sW + 128 * 128;       // 64
    const int tid = threadIdx.x;
    const int row0 = blockIdx.x * 64;

    if (tid < 64) {
        int r = row0 + tid;
        sCh[tid] = (r < NH) ? rsqrtf(fmaxf(g_deg_he[r], 1.f)) : 0.f;
    }
    for (int i = tid * 4; i < 64 * DD; i += 1024) {
        int r = i >> 7, c = i & 127;
        float4 v = make_float4(0.f, 0.f, 0.f, 0.f);
        if (row0 + r < NH) v = *(const float4*)&g_hyper_acc[(row0 + r) * DD + c];
        float* dstp = &sA[r * 129 + c];
        dstp[0] = v.x; dstp[1] = v.y; dstp[2] = v.z; dstp[3] = v.w;
    }
    for (int i = tid * 4; i < DD * DD; i += 1024)
        *(float4*)&sW[i] = *(const float4*)&W1[i];
    __syncthreads();

    const int rt = tid & 15, ct = tid >> 4;
    const int r0 = rt * 4, c0 = ct * 8, cp0 = c0 >> 1;
    const unsigned long long* sWu = (const unsigned long long*)sW;
    unsigned long long acc[4][4];
#pragma unroll
    for (int i = 0; i < 4; i++)
#pragma unroll
        for (int p = 0; p < 4; p++) acc[i][p] = 0ull;

    gemm_tile_k128(&sA[r0 * 129], 129, sWu, cp0, acc);

#pragma unroll
    for (int i = 0; i < 4; i++) {
        int gr = row0 + r0 + i;
        if (gr >= NH) continue;
        float ch = sCh[r0 + i];
        float ch2 = ch * ch;
#pragma unroll
        for (int p = 0; p < 4; p++) {
            float x, y;
            f2_unpack(acc[i][p], x, y);
            int c = c0 + 2 * p;
            float2 o;
            o.x = x * ch2 + __ldg(&b1[c]) * ch;
            o.y = y * ch2 + __ldg(&b1[c + 1]) * ch;
            *(float2*)&g_hyper_msg[gr * DD + c] = o;
        }
    }
}

// ---------------- K4: scatter hyper -> node ----------------
__global__ void k_scatter2(const int* __restrict__ src, const int* __restrict__ dst) {
    int e = blockIdx.x * 8 + (threadIdx.x >> 5);
    if (e >= NE) return;
    int lane = threadIdx.x & 31;
    int s = __ldg(&src[e]);
    int d = __ldg(&dst[e]);
    float4 v = __ldg(&((const float4*)g_hyper_msg)[d * 32 + lane]);
    float* p = &g_node_acc[s * DD + lane * 4];
    asm volatile("red.global.add.v4.f32 [%0], {%1, %2, %3, %4};"
                 :: "l"(p), "f"(v.x), "f"(v.y), "f"(v.z), "f"(v.w) : "memory");
}

// ---------------- K5: fused GEMM2 + resid + LN1 + FFN + resid + LN2 ----------------
// smem: sA[64*129] (h1), sH[64*513] (acc-in / hid / pre-LN2), sW[128*128], sCn[64]
__global__ void k_fused(const float* __restrict__ h, const float* __restrict__ W2,
                        const float* __restrict__ b2, const float* __restrict__ W3,
                        const float* __restrict__ b3, const float* __restrict__ W4,
                        const float* __restrict__ b4, const float* __restrict__ g1,
                        const float* __restrict__ be1, const float* __restrict__ g2,
                        const float* __restrict__ be2, float* __restrict__ out) {
    extern __shared__ float sm[];
    float* sA = sm;                      // 64 x 129
    float* sH = sA + 64 * 129;           // 64 x 513
    float* sW = sH + 64 * 513;           // 128 x 128
    float* sCn = sW + 128 * 128;         // 64
    const int tid = threadIdx.x;
    const int row0 = blockIdx.x * 64;
    const int warp = tid >> 5, lane = tid & 31;

    if (tid < 64) {
        int r = row0 + tid;
        sCn[tid] = (r < NN) ? rsqrtf(fmaxf(g_deg_node[r], 1.f)) : 0.f;
    }
    // node_acc -> sH (stride 513)
    for (int i = tid * 4; i < 64 * DD; i += 1024) {
        int r = i >> 7, c = i & 127;
        float4 v = make_float4(0.f, 0.f, 0.f, 0.f);
        if (row0 + r < NN) v = *(const float4*)&g_node_acc[(row0 + r) * DD + c];
        float* dstp = &sH[r * 513 + c];
        dstp[0] = v.x; dstp[1] = v.y; dstp[2] = v.z; dstp[3] = v.w;
    }
    // W2 -> sW
    for (int i = tid * 4; i < DD * DD; i += 1024)
        *(float4*)&sW[i] = *(const float4*)&W2[i];
    __syncthreads();

    const int rt = tid & 15, ct = tid >> 4;
    const int r0 = rt * 4, c0 = ct * 8, cp0 = c0 >> 1;
    const unsigned long long* sWu = (const unsigned long long*)sW;

    // ---- GEMM2: dot = acc @ W2 ----
    unsigned long long acc[4][4];
#pragma unroll
    for (int i = 0; i < 4; i++)
#pragma unroll
        for (int p = 0; p < 4; p++) acc[i][p] = 0ull;
    gemm_tile_k128(&sH[r0 * 513], 513, sWu, cp0, acc);

    // epilogue: h + (cn*dot + b2) -> sA
#pragma unroll
    for (int i = 0; i < 4; i++) {
        int rr = r0 + i;
        int gr = row0 + rr;
        float cn = sCn[rr];
#pragma unroll
        for (int p = 0; p < 4; p++) {
            float x, y;
            f2_unpack(acc[i][p], x, y);
            int c = c0 + 2 * p;
            float hx = 0.f, hy = 0.f;
            if (gr < NN) {
                float2 hv = *(const float2*)&h[gr * DD + c];
                hx = hv.x; hy = hv.y;
            }
            sA[rr * 129 + c]     = x * cn + __ldg(&b2[c]) + hx;
            sA[rr * 129 + c + 1] = y * cn + __ldg(&b2[c + 1]) + hy;
        }
    }
    __syncthreads();

    // ---- LN1 in place on sA ----
    {
        float gg[4], bb[4];
#pragma unroll
        for (int q = 0; q < 4; q++) {
            gg[q] = __ldg(&g1[lane + 32 * q]);
            bb[q] = __ldg(&be1[lane + 32 * q]);
        }
        for (int rr = warp * 8; rr < warp * 8 + 8; ++rr) {
            float* row = &sA[rr * 129];
            float v[4];
            float s = 0.f;
#pragma unroll
            for (int q = 0; q < 4; q++) { v[q] = row[lane + 32 * q]; s += v[q]; }
#pragma unroll
            for (int o = 16; o; o >>= 1) s += __shfl_xor_sync(0xffffffffu, s, o);
            float mu = s * 0.0078125f;
            float qs = 0.f;
#pragma unroll
            for (int q = 0; q < 4; q++) { v[q] -= mu; qs += v[q] * v[q]; }
#pragma unroll
            for (int o = 16; o; o >>= 1) qs += __shfl_xor_sync(0xffffffffu, qs, o);
            float inv = rsqrtf(qs * 0.0078125f + 1e-5f);
#pragma unroll
            for (int q = 0; q < 4; q++) row[lane + 32 * q] = v[q] * inv * gg[q] + bb[q];
        }
    }
    __syncthreads();

    // ---- FFN phase A: hid = relu(h1 @ W3 + b3), 4 n-chunks of 128 ----
    for (int nc = 0; nc < 4; nc++) {
        __syncthreads();
        for (int i = tid * 4; i < DD * DD; i += 1024) {
            int k = i >> 7, j = i & 127;
            *(float4*)&sW[k * 128 + j] = *(const float4*)&W3[k * HH + nc * 128 + j];
        }
        __syncthreads();
        unsigned long long bp[4];
#pragma unroll
        for (int p = 0; p < 4; p++) {
            float2 bv = *(const float2*)&b3[nc * 128 + c0 + 2 * p];
            bp[p] = f2_pack(bv.x, bv.y);
        }
        unsigned long long acc2[4][4];
#pragma unroll
        for (int i = 0; i < 4; i++)
#pragma unroll
            for (int p = 0; p < 4; p++) acc2[i][p] = bp[p];
        gemm_tile_k128(&sA[r0 * 129], 129, sWu, cp0, acc2);
#pragma unroll
        for (int i = 0; i < 4; i++) {
            int rbase = (r0 + i) * 513 + nc * 128 + c0;
#pragma unroll
            for (int p = 0; p < 4; p++) {
                float x, y;
                f2_unpack(acc2[i][p], x, y);
                sH[rbase + 2 * p]     = fmaxf(x, 0.f);
                sH[rbase + 2 * p + 1] = fmaxf(y, 0.f);
            }
        }
    }

    // ---- FFN phase B: out = hid @ W4 + b4, 4 k-chunks of 128 ----
    unsigned long long acc3[4][4];
#pragma unroll
    for (int p = 0; p < 4; p++) {
        float2 bv = *(const float2*)&b4[c0 + 2 * p];
        unsigned long long bp = f2_pack(bv.x, bv.y);
#pragma unroll
        for (int i = 0; i < 4; i++) acc3[i][p] = bp;
    }
    for (int kc = 0; kc < 4; kc++) {
        __syncthreads();
        for (int i = tid * 4; i < DD * DD; i += 1024)
            *(float4*)&sW[i] = *(const float4*)&W4[kc * 16384 + i];
        __syncthreads();
        gemm_tile_k128(&sH[r0 * 513 + kc * 128], 513, sWu, cp0, acc3);
    }
    __syncthreads();

    // epilogue: val = ffn + h1 -> sH (first 128 cols)
#pragma unroll
    for (int i = 0; i < 4; i++) {
        int rr = r0 + i;
#pragma unroll
        for (int p = 0; p < 4; p++) {
            float x, y;
            f2_unpack(acc3[i][p], x, y);
            int c = c0 + 2 * p;
            sH[rr * 513 + c]     = x + sA[rr * 129 + c];
            sH[rr * 513 + c + 1] = y + sA[rr * 129 + c + 1];
        }
    }
    __syncthreads();

    // ---- LN2 -> out ----
    {
        float gg[4], bb[4];
#pragma unroll
        for (int q = 0; q < 4; q++) {
            gg[q] = __ldg(&g2[lane + 32 * q]);
            bb[q] = __ldg(&be2[lane + 32 * q]);
        }
        for (int rr = warp * 8; rr < warp * 8 + 8; ++rr) {
            int gr = row0 + rr;
            float* row = &sH[rr * 513];
            float v[4];
            float s = 0.f;
#pragma unroll
            for (int q = 0; q < 4; q++) { v[q] = row[lane + 32 * q]; s += v[q]; }
#pragma unroll
            for (int o = 16; o; o >>= 1) s += __shfl_xor_sync(0xffffffffu, s, o);
            float mu = s * 0.0078125f;
            float qs = 0.f;
#pragma unroll
            for (int q = 0; q < 4; q++) { v[q] -= mu; qs += v[q] * v[q]; }
#pragma unroll
            for (int o = 16; o; o >>= 1) qs += __shfl_xor_sync(0xffffffffu, qs, o);
            float inv = rsqrtf(qs * 0.0078125f + 1e-5f);
            if (gr < NN) {
#pragma unroll
                for (int q = 0; q < 4; q++)
                    out[gr * DD + lane + 32 * q] = v[q] * inv * gg[q] + bb[q];
            }
        }
    }
}

// ---------------- launch ----------------
#define SMEM_GEMM1 ((64 * 129 + 128 * 128 + 64) * (int)sizeof(float))
#define SMEM_FUSED ((64 * 129 + 64 * 513 + 128 * 128 + 64) * (int)sizeof(float))

extern "C" void kernel_launch(void* const* d_in, const int* in_sizes, int n_in,
                              void* d_out, int out_size) {
    const float* h   = (const float*)d_in[0];
    const int*   src = (const int*)d_in[1];
    const int*   dst = (const int*)d_in[2];
    const float* W1  = (const float*)d_in[3];
    const float* b1  = (const float*)d_in[4];
    const float* W2  = (const float*)d_in[5];
    const float* b2  = (const float*)d_in[6];
    const float* W3  = (const float*)d_in[7];
    const float* b3  = (const float*)d_in[8];
    const float* W4  = (const float*)d_in[9];
    const float* b4  = (const float*)d_in[10];
    const float* g1  = (const float*)d_in[11];
    const float* be1 = (const float*)d_in[12];
    const float* g2  = (const float*)d_in[13];
    const float* be2 = (const float*)d_in[14];
    float* out = (float*)d_out;

    cudaFuncSetAttribute(k_gemm1, cudaFuncAttributeMaxDynamicSharedMemorySize, SMEM_GEMM1);
    cudaFuncSetAttribute(k_fused, cudaFuncAttributeMaxDynamicSharedMemorySize, SMEM_FUSED);

    k_zero<<<2048, 256>>>();
    k_deg<<<(NE + 255) / 256, 256>>>(src, dst);
    k_scatter1<<<NE / 8, 256>>>(h, src, dst);
    k_gemm1<<<(NH + 63) / 64, 256, SMEM_GEMM1>>>(W1, b1);
    k_scatter2<<<NE / 8, 256>>>(src, dst);
    k_fused<<<(NN + 63) / 64, 256, SMEM_FUSED>>>(h, W2, b2, W3, b3, W4, b4,
                                                 g1, be1, g2, be2, out);
}

// round 5
// speedup vs baseline: 1.6072x; 1.6072x over previous
#include <cuda_runtime.h>
#include <cuda_bf16.h>
#include <cstdint>

#define NN 100000
#define NH 20000
#define NE 1600000
#define DD 128
#define HH 512

// ---------------- scratch (device globals; no allocation allowed) ----------------
__device__ __align__(16) float g_deg_node[NN];
__device__ __align__(16) float g_deg_he[NH];
__device__ __align__(16) float g_hyper_acc[NH * DD];
__device__ __align__(16) float g_hyper_msg[NH * DD];
__device__ __align__(16) float g_node_acc[NN * DD];
// pre-transposed bf16 hi/lo weight planes: [n][k] layout
__device__ __align__(16) __nv_bfloat16 g_w2t_h[DD * DD];
__device__ __align__(16) __nv_bfloat16 g_w2t_l[DD * DD];
__device__ __align__(16) __nv_bfloat16 g_w3t_h[HH * DD];   // [n=0..511][k=0..127]
__device__ __align__(16) __nv_bfloat16 g_w3t_l[HH * DD];
__device__ __align__(16) __nv_bfloat16 g_w4t_h[DD * HH];   // [n=0..127][kk=0..511]
__device__ __align__(16) __nv_bfloat16 g_w4t_l[DD * HH];

// ---------------- packed fp32x2 helpers ----------------
__device__ __forceinline__ unsigned long long f2_pack(float x, float y) {
    unsigned long long r;
    asm("mov.b64 %0, {%1, %2};" : "=l"(r) : "f"(x), "f"(y));
    return r;
}
__device__ __forceinline__ void f2_unpack(unsigned long long v, float& x, float& y) {
    asm("mov.b64 {%0, %1}, %2;" : "=f"(x), "=f"(y) : "l"(v));
}
__device__ __forceinline__ unsigned long long ffma2(unsigned long long a,
                                                    unsigned long long b,
                                                    unsigned long long c) {
    unsigned long long d;
    asm("fma.rn.f32x2 %0, %1, %2, %3;" : "=l"(d) : "l"(a), "l"(b), "l"(c));
    return d;
}

__device__ __forceinline__ void gemm_tile_k128(const float* __restrict__ a_base, int a_stride,
                                               const unsigned long long* __restrict__ w_base,
                                               int cp0, unsigned long long acc[4][4]) {
#pragma unroll 8
    for (int k = 0; k < 128; k++) {
        unsigned long long A[4];
#pragma unroll
        for (int i = 0; i < 4; i++) {
            float a = a_base[i * a_stride + k];
            A[i] = f2_pack(a, a);
        }
        unsigned long long w[4];
#pragma unroll
        for (int p = 0; p < 4; p++) w[p] = w_base[k * 64 + cp0 + p];
#pragma unroll
        for (int i = 0; i < 4; i++)
#pragma unroll
            for (int p = 0; p < 4; p++) acc[i][p] = ffma2(A[i], w[p], acc[i][p]);
    }
}

// =================== small kernels ===================
__global__ void k_zero() {
    int idx = blockIdx.x * blockDim.x + threadIdx.x;
    int nthr = gridDim.x * blockDim.x;
    float4 z = make_float4(0.f, 0.f, 0.f, 0.f);
    for (int i = idx; i < NN * DD / 4; i += nthr) ((float4*)g_node_acc)[i] = z;
    for (int i = idx; i < NH * DD / 4; i += nthr) ((float4*)g_hyper_acc)[i] = z;
    for (int i = idx; i < NN; i += nthr) g_deg_node[i] = 0.f;
    for (int i = idx; i < NH; i += nthr) g_deg_he[i] = 0.f;
}

__global__ void k_deg(const int* __restrict__ src, const int* __restrict__ dst) {
    int e = blockIdx.x * blockDim.x + threadIdx.x;
    if (e < NE) {
        atomicAdd(&g_deg_node[src[e]], 1.f);
        atomicAdd(&g_deg_he[dst[e]], 1.f);
    }
}

// weight transpose + bf16 hi/lo precompute (once per launch)
__global__ void k_wconv(const float* __restrict__ W2, const float* __restrict__ W3,
                        const float* __restrict__ W4) {
    int idx0 = blockIdx.x * blockDim.x + threadIdx.x;
    int nt = gridDim.x * blockDim.x;
    for (int i = idx0; i < DD * DD; i += nt) {
        int n = i >> 7, k = i & 127;
        float v = W2[k * DD + n];
        __nv_bfloat16 hi = __float2bfloat16(v);
        g_w2t_h[i] = hi;
        g_w2t_l[i] = __float2bfloat16(v - __bfloat162float(hi));
    }
    for (int i = idx0; i < HH * DD; i += nt) {
        int n = i >> 7, k = i & 127;
        float v = W3[k * HH + n];
        __nv_bfloat16 hi = __float2bfloat16(v);
        g_w3t_h[i] = hi;
        g_w3t_l[i] = __float2bfloat16(v - __bfloat162float(hi));
    }
    for (int i = idx0; i < DD * HH; i += nt) {
        int n = i >> 9, kk = i & 511;
        float v = W4[kk * DD + n];
        __nv_bfloat16 hi = __float2bfloat16(v);
        g_w4t_h[i] = hi;
        g_w4t_l[i] = __float2bfloat16(v - __bfloat162float(hi));
    }
}

__global__ void k_scatter1(const float* __restrict__ h, const int* __restrict__ src,
                           const int* __restrict__ dst) {
    int e = blockIdx.x * 8 + (threadIdx.x >> 5);
    if (e >= NE) return;
    int lane = threadIdx.x & 31;
    int s = __ldg(&src[e]);
    int d = __ldg(&dst[e]);
    float cn = rsqrtf(fmaxf(g_deg_node[s], 1.f));
    float4 v = __ldg(&((const float4*)h)[s * 32 + lane]);
    v.x *= cn; v.y *= cn; v.z *= cn; v.w *= cn;
    float* p = &g_hyper_acc[d * DD + lane * 4];
    asm volatile("red.global.add.v4.f32 [%0], {%1, %2, %3, %4};"
                 :: "l"(p), "f"(v.x), "f"(v.y), "f"(v.z), "f"(v.w) : "memory");
}

__global__ void k_gemm1(const float* __restrict__ W1, const float* __restrict__ b1) {
    extern __shared__ float smf[];
    float* sA = smf;                   // 64 x 129
    float* sW = sA + 64 * 129;         // 128 x 128
    float* sCh = sW + 128 * 128;       // 64
    const int tid = threadIdx.x;
    const int row0 = blockIdx.x * 64;

    if (tid < 64) {
        int r = row0 + tid;
        sCh[tid] = (r < NH) ? rsqrtf(fmaxf(g_deg_he[r], 1.f)) : 0.f;
    }
    for (int i = tid * 4; i < 64 * DD; i += 1024) {
        int r = i >> 7, c = i & 127;
        float4 v = make_float4(0.f, 0.f, 0.f, 0.f);
        if (row0 + r < NH) v = *(const float4*)&g_hyper_acc[(row0 + r) * DD + c];
        float* dstp = &sA[r * 129 + c];
        dstp[0] = v.x; dstp[1] = v.y; dstp[2] = v.z; dstp[3] = v.w;
    }
    for (int i = tid * 4; i < DD * DD; i += 1024)
        *(float4*)&sW[i] = *(const float4*)&W1[i];
    __syncthreads();

    const int rt = tid & 15, ct = tid >> 4;
    const int r0 = rt * 4, c0 = ct * 8, cp0 = c0 >> 1;
    const unsigned long long* sWu = (const unsigned long long*)sW;
    unsigned long long acc[4][4];
#pragma unroll
    for (int i = 0; i < 4; i++)
#pragma unroll
        for (int p = 0; p < 4; p++) acc[i][p] = 0ull;

    gemm_tile_k128(&sA[r0 * 129], 129, sWu, cp0, acc);

#pragma unroll
    for (int i = 0; i < 4; i++) {
        int gr = row0 + r0 + i;
        if (gr >= NH) continue;
        float ch = sCh[r0 + i];
        float ch2 = ch * ch;
#pragma unroll
        for (int p = 0; p < 4; p++) {
            float x, y;
            f2_unpack(acc[i][p], x, y);
            int c = c0 + 2 * p;
            float2 o;
            o.x = x * ch2 + __ldg(&b1[c]) * ch;
            o.y = y * ch2 + __ldg(&b1[c + 1]) * ch;
            *(float2*)&g_hyper_msg[gr * DD + c] = o;
        }
    }
}

__global__ void k_scatter2(const int* __restrict__ src, const int* __restrict__ dst) {
    int e = blockIdx.x * 8 + (threadIdx.x >> 5);
    if (e >= NE) return;
    int lane = threadIdx.x & 31;
    int s = __ldg(&src[e]);
    int d = __ldg(&dst[e]);
    float4 v = __ldg(&((const float4*)g_hyper_msg)[d * 32 + lane]);
    float* p = &g_node_acc[s * DD + lane * 4];
    asm volatile("red.global.add.v4.f32 [%0], {%1, %2, %3, %4};"
                 :: "l"(p), "f"(v.x), "f"(v.y), "f"(v.z), "f"(v.w) : "memory");
}

// =================== HMMA fused kernel ===================
// smem plane: 128 rows x 272B (136 bf16), conflict-free for frag loads
#define STR 272
#define SM_CN   0
#define SM_B2   512
#define SM_B4   1024
#define SM_G1   1536
#define SM_BE1  2048
#define SM_G2   2560
#define SM_BE2  3072
#define SM_B3   3584
#define SM_A1H  5632
#define SM_A1L  (SM_A1H + 128 * STR)
#define SM_A2H  (SM_A1L + 128 * STR)
#define SM_A2L  (SM_A2H + 128 * STR)
#define SM_WH   (SM_A2L + 128 * STR)
#define SM_WL   (SM_WH + 128 * STR)
#define SM_TOTAL (SM_WL + 128 * STR)

__device__ __forceinline__ void mma_bf16(float d[4], uint32_t a0, uint32_t a1,
                                         uint32_t a2, uint32_t a3,
                                         uint32_t b0, uint32_t b1) {
    asm volatile(
        "mma.sync.aligned.m16n8k16.row.col.f32.bf16.bf16.f32 "
        "{%0,%1,%2,%3}, {%4,%5,%6,%7}, {%8,%9}, {%0,%1,%2,%3};"
        : "+f"(d[0]), "+f"(d[1]), "+f"(d[2]), "+f"(d[3])
        : "r"(a0), "r"(a1), "r"(a2), "r"(a3), "r"(b0), "r"(b1));
}

// store adjacent col pair (c even) as bf16 hi/lo planes
__device__ __forceinline__ void sts_hilo(char* pH, char* pL, float x0, float x1) {
    __nv_bfloat16 h0 = __float2bfloat16(x0), h1 = __float2bfloat16(x1);
    float r0f = x0 - __bfloat162float(h0), r1f = x1 - __bfloat162float(h1);
    *(__nv_bfloat162*)pH = __halves2bfloat162(h0, h1);
    *(__nv_bfloat162*)pL = __halves2bfloat162(__float2bfloat16(r0f), __float2bfloat16(r1f));
}

// D[16 warp-rows x 128] += A[16x128] @ W^T[128x128], 3-term hi/lo
__device__ __forceinline__ void gemm128(const char* smc, int aHoff, int aLoff,
                                        int r0, int g, int t, float d[16][4]) {
    const char* pAH = smc + aHoff + (r0 + g) * STR + t * 4;
    const char* pAL = smc + aLoff + (r0 + g) * STR + t * 4;
    const char* pBH = smc + SM_WH + g * STR + t * 4;
    const char* pBL = smc + SM_WL + g * STR + t * 4;
#pragma unroll 1
    for (int k = 0; k < 8; k++) {
        uint32_t ah0 = *(const uint32_t*)(pAH);
        uint32_t ah1 = *(const uint32_t*)(pAH + 8 * STR);
        uint32_t ah2 = *(const uint32_t*)(pAH + 16);
        uint32_t ah3 = *(const uint32_t*)(pAH + 8 * STR + 16);
        uint32_t al0 = *(const uint32_t*)(pAL);
        uint32_t al1 = *(const uint32_t*)(pAL + 8 * STR);
        uint32_t al2 = *(const uint32_t*)(pAL + 16);
        uint32_t al3 = *(const uint32_t*)(pAL + 8 * STR + 16);
#pragma unroll
        for (int j = 0; j < 16; j++) {
            const char* bH = pBH + j * 8 * STR;
            const char* bL = pBL + j * 8 * STR;
            uint32_t bh0 = *(const uint32_t*)(bH);
            uint32_t bh1 = *(const uint32_t*)(bH + 16);
            uint32_t bl0 = *(const uint32_t*)(bL);
            uint32_t bl1 = *(const uint32_t*)(bL + 16);
            mma_bf16(d[j], ah0, ah1, ah2, ah3, bh0, bh1);
            mma_bf16(d[j], al0, al1, al2, al3, bh0, bh1);
            mma_bf16(d[j], ah0, ah1, ah2, ah3, bl0, bl1);
        }
        pAH += 32; pAL += 32; pBH += 32; pBL += 32;
    }
}

// copy one 128x128 bf16 plane pair (row stride srcStride elems) into WH/WL
__device__ __forceinline__ void stage_w(char* smc, const __nv_bfloat16* srcH,
                                        const __nv_bfloat16* srcL, int srcStride) {
    int tid = threadIdx.x;
#pragma unroll
    for (int i = tid; i < 2048; i += 256) {
        int r = i >> 4, c8 = (i & 15) * 8;
        uint4 vh = *(const uint4*)(srcH + r * srcStride + c8);
        uint4 vl = *(const uint4*)(srcL + r * srcStride + c8);
        *(uint4*)(smc + SM_WH + r * STR + c8 * 2) = vh;
        *(uint4*)(smc + SM_WL + r * STR + c8 * 2) = vl;
    }
}

__global__ __launch_bounds__(256, 1) void k_fused_mma(
    const float* __restrict__ h, const float* __restrict__ b2f,
    const float* __restrict__ b3f, const float* __restrict__ b4f,
    const float* __restrict__ g1f, const float* __restrict__ be1f,
    const float* __restrict__ g2f, const float* __restrict__ be2f,
    float* __restrict__ out) {
    extern __shared__ char smc[];
    const int tid = threadIdx.x;
    const int warp = tid >> 5, lane = tid & 31;
    const int g = lane >> 2, t = lane & 3;
    const int row0 = blockIdx.x * 128;
    const int r0 = warp * 16;

    // small arrays
    if (tid < 128) {
        int r = row0 + tid;
        ((float*)(smc + SM_CN))[tid]  = (r < NN) ? rsqrtf(fmaxf(g_deg_node[r], 1.f)) : 0.f;
        ((float*)(smc + SM_B2))[tid]  = b2f[tid];
        ((float*)(smc + SM_B4))[tid]  = b4f[tid];
        ((float*)(smc + SM_G1))[tid]  = g1f[tid];
        ((float*)(smc + SM_BE1))[tid] = be1f[tid];
        ((float*)(smc + SM_G2))[tid]  = g2f[tid];
        ((float*)(smc + SM_BE2))[tid] = be2f[tid];
    }
    for (int i = tid; i < 512; i += 256) ((float*)(smc + SM_B3))[i] = b3f[i];

    // A1 <- node_acc (fp32 -> bf16 hi/lo planes)
#pragma unroll
    for (int i = tid; i < 4096; i += 256) {
        int r = i >> 5, c4 = (i & 31) * 4;
        float4 v = make_float4(0.f, 0.f, 0.f, 0.f);
        if (row0 + r < NN) v = *(const float4*)&g_node_acc[(row0 + r) * DD + c4];
        char* pH = smc + SM_A1H + r * STR + c4 * 2;
        char* pL = smc + SM_A1L + r * STR + c4 * 2;
        sts_hilo(pH, pL, v.x, v.y);
        sts_hilo(pH + 4, pL + 4, v.z, v.w);
    }
    stage_w(smc, g_w2t_h, g_w2t_l, 128);
    __syncthreads();

    const int gr0 = row0 + r0 + g, gr1 = gr0 + 8;
    const float cn0 = ((float*)(smc + SM_CN))[r0 + g];
    const float cn1 = ((float*)(smc + SM_CN))[r0 + g + 8];

    // ---- GEMM2 ----
    float dA[16][4];
#pragma unroll
    for (int j = 0; j < 16; j++)
#pragma unroll
        for (int p = 0; p < 4; p++) dA[j][p] = 0.f;
    gemm128(smc, SM_A1H, SM_A1L, r0, g, t, dA);

    // ---- epilogue: h1 = LN1(h + cn*D + b2) -> A1 planes ----
    {
        const float* b2s = (const float*)(smc + SM_B2);
        float s0 = 0.f, q0 = 0.f, s1 = 0.f, q1 = 0.f;
#pragma unroll
        for (int j = 0; j < 16; j++) {
            int c = 8 * j + 2 * t;
            float2 h0 = make_float2(0.f, 0.f), h1v = make_float2(0.f, 0.f);
            if (gr0 < NN) h0 = *(const float2*)&h[gr0 * DD + c];
            if (gr1 < NN) h1v = *(const float2*)&h[gr1 * DD + c];
            float x0 = h0.x + cn0 * dA[j][0] + b2s[c];
            float x1 = h0.y + cn0 * dA[j][1] + b2s[c + 1];
            float x2 = h1v.x + cn1 * dA[j][2] + b2s[c];
            float x3 = h1v.y + cn1 * dA[j][3] + b2s[c + 1];
            dA[j][0] = x0; dA[j][1] = x1; dA[j][2] = x2; dA[j][3] = x3;
            s0 += x0 + x1; q0 += x0 * x0 + x1 * x1;
            s1 += x2 + x3; q1 += x2 * x2 + x3 * x3;
        }
        s0 += __shfl_xor_sync(~0u, s0, 1); s0 += __shfl_xor_sync(~0u, s0, 2);
        q0 += __shfl_xor_sync(~0u, q0, 1); q0 += __shfl_xor_sync(~0u, q0, 2);
        s1 += __shfl_xor_sync(~0u, s1, 1); s1 += __shfl_xor_sync(~0u, s1, 2);
        q1 += __shfl_xor_sync(~0u, q1, 1); q1 += __shfl_xor_sync(~0u, q1, 2);
        float mu0 = s0 * (1.f / 128.f), mu1 = s1 * (1.f / 128.f);
        float inv0 = rsqrtf(fmaxf(q0 * (1.f / 128.f) - mu0 * mu0, 0.f) + 1e-5f);
        float inv1 = rsqrtf(fmaxf(q1 * (1.f / 128.f) - mu1 * mu1, 0.f) + 1e-5f);
        const float* g1s = (const float*)(smc + SM_G1);
        const float* be1s = (const float*)(smc + SM_BE1);
#pragma unroll
        for (int j = 0; j < 16; j++) {
            int c = 8 * j + 2 * t;
            float y0 = (dA[j][0] - mu0) * inv0 * g1s[c] + be1s[c];
            float y1 = (dA[j][1] - mu0) * inv0 * g1s[c + 1] + be1s[c + 1];
            float y2 = (dA[j][2] - mu1) * inv1 * g1s[c] + be1s[c];
            float y3 = (dA[j][3] - mu1) * inv1 * g1s[c + 1] + be1s[c + 1];
            char* pH = smc + SM_A1H + (r0 + g) * STR + c * 2;
            char* pL = smc + SM_A1L + (r0 + g) * STR + c * 2;
            sts_hilo(pH, pL, y0, y1);
            sts_hilo(pH + 8 * STR, pL + 8 * STR, y2, y3);
        }
    }

    // ---- FFN: 4 hidden chunks; dC accumulates second GEMM ----
    float dC[16][4];
#pragma unroll
    for (int j = 0; j < 16; j++)
#pragma unroll
        for (int p = 0; p < 4; p++) dC[j][p] = 0.f;

    for (int nc = 0; nc < 4; nc++) {
        __syncthreads();
        stage_w(smc, g_w3t_h + nc * 128 * DD, g_w3t_l + nc * 128 * DD, 128);
        __syncthreads();
        float dB[16][4];
#pragma unroll
        for (int j = 0; j < 16; j++)
#pragma unroll
            for (int p = 0; p < 4; p++) dB[j][p] = 0.f;
        gemm128(smc, SM_A1H, SM_A1L, r0, g, t, dB);
        const float* b3s = (const float*)(smc + SM_B3) + nc * 128;
#pragma unroll
        for (int j = 0; j < 16; j++) {
            int c = 8 * j + 2 * t;
            float x0 = fmaxf(dB[j][0] + b3s[c], 0.f);
            float x1 = fmaxf(dB[j][1] + b3s[c + 1], 0.f);
            float x2 = fmaxf(dB[j][2] + b3s[c], 0.f);
            float x3 = fmaxf(dB[j][3] + b3s[c + 1], 0.f);
            char* pH = smc + SM_A2H + (r0 + g) * STR + c * 2;
            char* pL = smc + SM_A2L + (r0 + g) * STR + c * 2;
            sts_hilo(pH, pL, x0, x1);
            sts_hilo(pH + 8 * STR, pL + 8 * STR, x2, x3);
        }
        __syncthreads();
        stage_w(smc, g_w4t_h + nc * 128, g_w4t_l + nc * 128, 512);
        __syncthreads();
        gemm128(smc, SM_A2H, SM_A2L, r0, g, t, dC);
    }

    // ---- final epilogue: LN2(D2 + b4 + h1) -> out ----
    {
        const float* b4s = (const float*)(smc + SM_B4);
        float s0 = 0.f, q0 = 0.f, s1 = 0.f, q1 = 0.f;
#pragma unroll
        for (int j = 0; j < 16; j++) {
            int c = 8 * j + 2 * t;
            const char* pH = smc + SM_A1H + (r0 + g) * STR + c * 2;
            const char* pL = smc + SM_A1L + (r0 + g) * STR + c * 2;
            __nv_bfloat162 hh0 = *(const __nv_bfloat162*)(pH);
            __nv_bfloat162 ll0 = *(const __nv_bfloat162*)(pL);
            __nv_bfloat162 hh1 = *(const __nv_bfloat162*)(pH + 8 * STR);
            __nv_bfloat162 ll1 = *(const __nv_bfloat162*)(pL + 8 * STR);
            float x0 = dC[j][0] + b4s[c] + __bfloat162float(hh0.x) + __bfloat162float(ll0.x);
            float x1 = dC[j][1] + b4s[c + 1] + __bfloat162float(hh0.y) + __bfloat162float(ll0.y);
            float x2 = dC[j][2] + b4s[c] + __bfloat162float(hh1.x) + __bfloat162float(ll1.x);
            float x3 = dC[j][3] + b4s[c + 1] + __bfloat162float(hh1.y) + __bfloat162float(ll1.y);
            dC[j][0] = x0; dC[j][1] = x1; dC[j][2] = x2; dC[j][3] = x3;
            s0 += x0 + x1; q0 += x0 * x0 + x1 * x1;
            s1 += x2 + x3; q1 += x2 * x2 + x3 * x3;
        }
        s0 += __shfl_xor_sync(~0u, s0, 1); s0 += __shfl_xor_sync(~0u, s0, 2);
        q0 += __shfl_xor_sync(~0u, q0, 1); q0 += __shfl_xor_sync(~0u, q0, 2);
        s1 += __shfl_xor_sync(~0u, s1, 1); s1 += __shfl_xor_sync(~0u, s1, 2);
        q1 += __shfl_xor_sync(~0u, q1, 1); q1 += __shfl_xor_sync(~0u, q1, 2);
        float mu0 = s0 * (1.f / 128.f), mu1 = s1 * (1.f / 128.f);
        float inv0 = rsqrtf(fmaxf(q0 * (1.f / 128.f) - mu0 * mu0, 0.f) + 1e-5f);
        float inv1 = rsqrtf(fmaxf(q1 * (1.f / 128.f) - mu1 * mu1, 0.f) + 1e-5f);
        const float* g2s = (const float*)(smc + SM_G2);
        const float* be2s = (const float*)(smc + SM_BE2);
#pragma unroll
        for (int j = 0; j < 16; j++) {
            int c = 8 * j + 2 * t;
            if (gr0 < NN) {
                float2 o;
                o.x = (dC[j][0] - mu0) * inv0 * g2s[c] + be2s[c];
                o.y = (dC[j][1] - mu0) * inv0 * g2s[c + 1] + be2s[c + 1];
                *(float2*)&out[gr0 * DD + c] = o;
            }
            if (gr1 < NN) {
                float2 o;
                o.x = (dC[j][2] - mu1) * inv1 * g2s[c] + be2s[c];
                o.y = (dC[j][3] - mu1) * inv1 * g2s[c + 1] + be2s[c + 1];
                *(float2*)&out[gr1 * DD + c] = o;
            }
        }
    }
}

// ---------------- launch ----------------
#define SMEM_GEMM1 ((64 * 129 + 128 * 128 + 64) * (int)sizeof(float))

extern "C" void kernel_launch(void* const* d_in, const int* in_sizes, int n_in,
                              void* d_out, int out_size) {
    const float* h   = (const float*)d_in[0];
    const int*   src = (const int*)d_in[1];
    const int*   dst = (const int*)d_in[2];
    const float* W1  = (const float*)d_in[3];
    const float* b1  = (const float*)d_in[4];
    const float* W2  = (const float*)d_in[5];
    const float* b2  = (const float*)d_in[6];
    const float* W3  = (const float*)d_in[7];
    const float* b3  = (const float*)d_in[8];
    const float* W4  = (const float*)d_in[9];
    const float* b4  = (const float*)d_in[10];
    const float* g1  = (const float*)d_in[11];
    const float* be1 = (const float*)d_in[12];
    const float* g2  = (const float*)d_in[13];
    const float* be2 = (const float*)d_in[14];
    float* out = (float*)d_out;

    cudaFuncSetAttribute(k_gemm1, cudaFuncAttributeMaxDynamicSharedMemorySize, SMEM_GEMM1);
    cudaFuncSetAttribute(k_fused_mma, cudaFuncAttributeMaxDynamicSharedMemorySize, SM_TOTAL);

    k_zero<<<2048, 256>>>();
    k_wconv<<<288, 256>>>(W2, W3, W4);
    k_deg<<<(NE + 255) / 256, 256>>>(src, dst);
    k_scatter1<<<NE / 8, 256>>>(h, src, dst);
    k_gemm1<<<(NH + 63) / 64, 256, SMEM_GEMM1>>>(W1, b1);
    k_scatter2<<<NE / 8, 256>>>(src, dst);
    k_fused_mma<<<(NN + 127) / 128, 256, SM_TOTAL>>>(h, b2, b3, b4,
                                                     g1, be1, g2, be2, out);
}

// round 7
// speedup vs baseline: 1.8032x; 1.1220x over previous
#include <cuda_runtime.h>
#include <cuda_bf16.h>
#include <cstdint>

#define NN 100000
#define NH 20000
#define NE 1600000
#define DD 128
#define HH 512

// ---------------- scratch (device globals; no allocation allowed) ----------------
__device__ __align__(16) int g_degi_node[NN];
__device__ __align__(16) int g_degi_he[NH];
__device__ __align__(16) int g_off_node[NN + 1];
__device__ __align__(16) int g_off_he[NH + 1];
__device__ __align__(16) int g_cur_node[NN];
__device__ __align__(16) int g_cur_he[NH];
__device__ __align__(16) int g_srt_src[NE];     // edges sorted by dst -> src ids
__device__ __align__(16) int g_srt_dst[NE];     // edges sorted by src -> dst ids
__device__ __align__(16) float g_hs[NN * DD];   // cn * h
__device__ __align__(16) float g_hyper_acc[NH * DD];
__device__ __align__(16) float g_hyper_msg[NH * DD];
__device__ __align__(16) float g_node_acc[NN * DD];
// pre-transposed bf16 hi/lo weight planes: [n][k] layout
__device__ __align__(16) __nv_bfloat16 g_w1t_h[DD * DD];
__device__ __align__(16) __nv_bfloat16 g_w1t_l[DD * DD];
__device__ __align__(16) __nv_bfloat16 g_w2t_h[DD * DD];
__device__ __align__(16) __nv_bfloat16 g_w2t_l[DD * DD];
__device__ __align__(16) __nv_bfloat16 g_w3t_h[HH * DD];   // [n=0..511][k=0..127]
__device__ __align__(16) __nv_bfloat16 g_w3t_l[HH * DD];
__device__ __align__(16) __nv_bfloat16 g_w4t_h[DD * HH];   // [n=0..127][kk=0..511]
__device__ __align__(16) __nv_bfloat16 g_w4t_l[DD * HH];

// =================== preprocessing kernels ===================
__global__ void k_zero() {
    int idx = blockIdx.x * blockDim.x + threadIdx.x;
    int nthr = gridDim.x * blockDim.x;
    for (int i = idx; i < NN; i += nthr) { g_degi_node[i] = 0; g_cur_node[i] = 0; }
    for (int i = idx; i < NH; i += nthr) { g_degi_he[i] = 0; g_cur_he[i] = 0; }
}

__global__ void k_deg(const int* __restrict__ src, const int* __restrict__ dst) {
    int e = blockIdx.x * blockDim.x + threadIdx.x;
    if (e < NE) {
        atomicAdd(&g_degi_node[src[e]], 1);
        atomicAdd(&g_degi_he[dst[e]], 1);
    }
}

// single-block exclusive prefix scan over device globals.
// NOTE: device globals must be referenced from device code, NOT passed as
// host-side kernel args (host shadow address + ATS = silent garbage reads).
__global__ void k_scan(int which) {
    const int* __restrict__ cnt = which ? g_degi_node : g_degi_he;
    int* __restrict__ off = which ? g_off_node : g_off_he;
    const int n = which ? NN : NH;
    __shared__ int sh[1024];
    int tid = threadIdx.x;
    int chunk = (n + 1023) >> 10;
    int b = tid * chunk, e = b + chunk;
    if (b > n) b = n;
    if (e > n) e = n;
    int s = 0;
    for (int i = b; i < e; i++) s += cnt[i];
    sh[tid] = s;
    __syncthreads();
    for (int o = 1; o < 1024; o <<= 1) {
        int t = (tid >= o) ? sh[tid - o] : 0;
        __syncthreads();
        sh[tid] += t;
        __syncthreads();
    }
    int run = sh[tid] - s;
    for (int i = b; i < e; i++) { off[i] = run; run += cnt[i]; }
    if (tid == 1023) off[n] = sh[1023];
}

__global__ void k_place(const int* __restrict__ src, const int* __restrict__ dst) {
    int e = blockIdx.x * blockDim.x + threadIdx.x;
    if (e < NE) {
        int s = src[e], d = dst[e];
        int p1 = g_off_he[d] + atomicAdd(&g_cur_he[d], 1);
        g_srt_src[p1] = s;
        int p2 = g_off_node[s] + atomicAdd(&g_cur_node[s], 1);
        g_srt_dst[p2] = d;
    }
}

// h_scaled = cn * h
__global__ void k_scale_h(const float* __restrict__ h) {
    int i = blockIdx.x * blockDim.x + threadIdx.x;
    if (i < NN * 32) {
        int r = i >> 5;
        float cn = rsqrtf(fmaxf((float)g_degi_node[r], 1.f));
        float4 v = __ldg(&((const float4*)h)[i]);
        v.x *= cn; v.y *= cn; v.z *= cn; v.w *= cn;
        ((float4*)g_hs)[i] = v;
    }
}

// weight transpose + bf16 hi/lo precompute (once per launch)
__global__ void k_wconv(const float* __restrict__ W1, const float* __restrict__ W2,
                        const float* __restrict__ W3, const float* __restrict__ W4) {
    int idx0 = blockIdx.x * blockDim.x + threadIdx.x;
    int nt = gridDim.x * blockDim.x;
    for (int i = idx0; i < DD * DD; i += nt) {
        int n = i >> 7, k = i & 127;
        float v = W1[k * DD + n];
        __nv_bfloat16 hi = __float2bfloat16(v);
        g_w1t_h[i] = hi;
        g_w1t_l[i] = __float2bfloat16(v - __bfloat162float(hi));
        float v2 = W2[k * DD + n];
        __nv_bfloat16 hi2 = __float2bfloat16(v2);
        g_w2t_h[i] = hi2;
        g_w2t_l[i] = __float2bfloat16(v2 - __bfloat162float(hi2));
    }
    for (int i = idx0; i < HH * DD; i += nt) {
        int n = i >> 7, k = i & 127;
        float v = W3[k * HH + n];
        __nv_bfloat16 hi = __float2bfloat16(v);
        g_w3t_h[i] = hi;
        g_w3t_l[i] = __float2bfloat16(v - __bfloat162float(hi));
    }
    for (int i = idx0; i < DD * HH; i += nt) {
        int n = i >> 9, kk = i & 511;
        float v = W4[kk * DD + n];
        __nv_bfloat16 hi = __float2bfloat16(v);
        g_w4t_h[i] = hi;
        g_w4t_l[i] = __float2bfloat16(v - __bfloat162float(hi));
    }
}

// =================== segmented gathers (no atomics) ===================
// warp per hyperedge: hyper_acc[he] = sum over edges of hs[src]
__global__ void k_gather1() {
    int w = (blockIdx.x * blockDim.x + threadIdx.x) >> 5;
    if (w >= NH) return;
    int lane = threadIdx.x & 31;
    int beg = g_off_he[w], end = g_off_he[w + 1];
    float4 acc = make_float4(0.f, 0.f, 0.f, 0.f);
    for (int e = beg; e < end; e += 32) {
        int n = end - e;
        if (n > 32) n = 32;
        int idx = g_srt_src[e + (lane < n ? lane : 0)];
#pragma unroll 4
        for (int j = 0; j < n; j++) {
            int s = __shfl_sync(0xffffffffu, idx, j);
            float4 v = __ldg(&((const float4*)g_hs)[s * 32 + lane]);
            acc.x += v.x; acc.y += v.y; acc.z += v.z; acc.w += v.w;
        }
    }
    ((float4*)g_hyper_acc)[w * 32 + lane] = acc;
}

// warp per node: node_acc[nd] = sum over edges of hyper_msg[dst]
__global__ void k_gather2() {
    int w = (blockIdx.x * blockDim.x + threadIdx.x) >> 5;
    if (w >= NN) return;
    int lane = threadIdx.x & 31;
    int beg = g_off_node[w], end = g_off_node[w + 1];
    float4 acc = make_float4(0.f, 0.f, 0.f, 0.f);
    for (int e = beg; e < end; e += 32) {
        int n = end - e;
        if (n > 32) n = 32;
        int idx = g_srt_dst[e + (lane < n ? lane : 0)];
#pragma unroll 4
        for (int j = 0; j < n; j++) {
            int d = __shfl_sync(0xffffffffu, idx, j);
            float4 v = __ldg(&((const float4*)g_hyper_msg)[d * 32 + lane]);
            acc.x += v.x; acc.y += v.y; acc.z += v.z; acc.w += v.w;
        }
    }
    ((float4*)g_node_acc)[w * 32 + lane] = acc;
}

// =================== HMMA machinery ===================
#define STR 272

__device__ __forceinline__ void mma_bf16(float d[4], uint32_t a0, uint32_t a1,
                                         uint32_t a2, uint32_t a3,
                                         uint32_t b0, uint32_t b1) {
    asm volatile(
        "mma.sync.aligned.m16n8k16.row.col.f32.bf16.bf16.f32 "
        "{%0,%1,%2,%3}, {%4,%5,%6,%7}, {%8,%9}, {%0,%1,%2,%3};"
        : "+f"(d[0]), "+f"(d[1]), "+f"(d[2]), "+f"(d[3])
        : "r"(a0), "r"(a1), "r"(a2), "r"(a3), "r"(b0), "r"(b1));
}

__device__ __forceinline__ void sts_hilo(char* pH, char* pL, float x0, float x1) {
    __nv_bfloat16 h0 = __float2bfloat16(x0), h1 = __float2bfloat16(x1);
    float r0f = x0 - __bfloat162float(h0), r1f = x1 - __bfloat162float(h1);
    *(__nv_bfloat162*)pH = __halves2bfloat162(h0, h1);
    *(__nv_bfloat162*)pL = __halves2bfloat162(__float2bfloat16(r0f), __float2bfloat16(r1f));
}

// D[16 warp-rows x 128] += A[16x128] @ W^T[128x128], 3-term hi/lo
__device__ __forceinline__ void gemm128(const char* smc, int aHoff, int aLoff,
                                        int wHoff, int wLoff,
                                        int r0, int g, int t, float d[16][4]) {
    const char* pAH = smc + aHoff + (r0 + g) * STR + t * 4;
    const char* pAL = smc + aLoff + (r0 + g) * STR + t * 4;
    const char* pBH = smc + wHoff + g * STR + t * 4;
    const char* pBL = smc + wLoff + g * STR + t * 4;
#pragma unroll 1
    for (int k = 0; k < 8; k++) {
        uint32_t ah0 = *(const uint32_t*)(pAH);
        uint32_t ah1 = *(const uint32_t*)(pAH + 8 * STR);
        uint32_t ah2 = *(const uint32_t*)(pAH + 16);
        uint32_t ah3 = *(const uint32_t*)(pAH + 8 * STR + 16);
        uint32_t al0 = *(const uint32_t*)(pAL);
        uint32_t al1 = *(const uint32_t*)(pAL + 8 * STR);
        uint32_t al2 = *(const uint32_t*)(pAL + 16);
        uint32_t al3 = *(const uint32_t*)(pAL + 8 * STR + 16);
#pragma unroll
        for (int j = 0; j < 16; j++) {
            const char* bH = pBH + j * 8 * STR;
            const char* bL = pBL + j * 8 * STR;
            uint32_t bh0 = *(const uint32_t*)(bH);
            uint32_t bh1 = *(const uint32_t*)(bH + 16);
            uint32_t bl0 = *(const uint32_t*)(bL);
            uint32_t bl1 = *(const uint32_t*)(bL + 16);
            mma_bf16(d[j], ah0, ah1, ah2, ah3, bh0, bh1);
            mma_bf16(d[j], al0, al1, al2, al3, bh0, bh1);
            mma_bf16(d[j], ah0, ah1, ah2, ah3, bl0, bl1);
        }
        pAH += 32; pAL += 32; pBH += 32; pBL += 32;
    }
}

__device__ __forceinline__ void stage_w(char* smc, int wHoff, int wLoff,
                                        const __nv_bfloat16* srcH,
                                        const __nv_bfloat16* srcL, int srcStride) {
    int tid = threadIdx.x;
#pragma unroll
    for (int i = tid; i < 2048; i += 256) {
        int r = i >> 4, c8 = (i & 15) * 8;
        uint4 vh = *(const uint4*)(srcH + r * srcStride + c8);
        uint4 vl = *(const uint4*)(srcL + r * srcStride + c8);
        *(uint4*)(smc + wHoff + r * STR + c8 * 2) = vh;
        *(uint4*)(smc + wLoff + r * STR + c8 * 2) = vl;
    }
}

// ---- GEMM1 (hyper): g_hyper_msg = ch^2*(hyper_acc @ W1) + ch*b1 ----
#define SM1_CH 0
#define SM1_B1 512
#define SM1_AH 1024
#define SM1_AL (SM1_AH + 128 * STR)
#define SM1_WH (SM1_AL + 128 * STR)
#define SM1_WL (SM1_WH + 128 * STR)
#define SM1_TOTAL (SM1_WL + 128 * STR)

__global__ __launch_bounds__(256, 1) void k_gemm1_mma(const float* __restrict__ b1f) {
    extern __shared__ char smc[];
    const int tid = threadIdx.x;
    const int warp = tid >> 5, lane = tid & 31;
    const int g = lane >> 2, t = lane & 3;
    const int row0 = blockIdx.x * 128;
    const int r0 = warp * 16;

    if (tid < 128) {
        int r = row0 + tid;
        ((float*)(smc + SM1_CH))[tid] = (r < NH) ? rsqrtf(fmaxf((float)g_degi_he[r], 1.f)) : 0.f;
        ((float*)(smc + SM1_B1))[tid] = b1f[tid];
    }
#pragma unroll
    for (int i = tid; i < 4096; i += 256) {
        int r = i >> 5, c4 = (i & 31) * 4;
        float4 v = make_float4(0.f, 0.f, 0.f, 0.f);
        if (row0 + r < NH) v = *(const float4*)&g_hyper_acc[(row0 + r) * DD + c4];
        char* pH = smc + SM1_AH + r * STR + c4 * 2;
        char* pL = smc + SM1_AL + r * STR + c4 * 2;
        sts_hilo(pH, pL, v.x, v.y);
        sts_hilo(pH + 4, pL + 4, v.z, v.w);
    }
    stage_w(smc, SM1_WH, SM1_WL, g_w1t_h, g_w1t_l, 128);
    __syncthreads();

    float dA[16][4];
#pragma unroll
    for (int j = 0; j < 16; j++)
#pragma unroll
        for (int p = 0; p < 4; p++) dA[j][p] = 0.f;
    gemm128(smc, SM1_AH, SM1_AL, SM1_WH, SM1_WL, r0, g, t, dA);

    const int gr0 = row0 + r0 + g, gr1 = gr0 + 8;
    float ch0 = ((float*)(smc + SM1_CH))[r0 + g];
    float ch1 = ((float*)(smc + SM1_CH))[r0 + g + 8];
    float ch0q = ch0 * ch0, ch1q = ch1 * ch1;
    const float* b1s = (const float*)(smc + SM1_B1);
#pragma unroll
    for (int j = 0; j < 16; j++) {
        int c = 8 * j + 2 * t;
        if (gr0 < NH) {
            float2 o;
            o.x = dA[j][0] * ch0q + b1s[c] * ch0;
            o.y = dA[j][1] * ch0q + b1s[c + 1] * ch0;
            *(float2*)&g_hyper_msg[gr0 * DD + c] = o;
        }
        if (gr1 < NH) {
            float2 o;
            o.x = dA[j][2] * ch1q + b1s[c] * ch1;
            o.y = dA[j][3] * ch1q + b1s[c + 1] * ch1;
            *(float2*)&g_hyper_msg[gr1 * DD + c] = o;
        }
    }
}

// ---- fused GEMM2 + LN1 + FFN + LN2 ----
#define SM_CN   0
#define SM_B2   512
#define SM_B4   1024
#define SM_G1   1536
#define SM_BE1  2048
#define SM_G2   2560
#define SM_BE2  3072
#define SM_B3   3584
#define SM_A1H  5632
#define SM_A1L  (SM_A1H + 128 * STR)
#define SM_A2H  (SM_A1L + 128 * STR)
#define SM_A2L  (SM_A2H + 128 * STR)
#define SM_WH   (SM_A2L + 128 * STR)
#define SM_WL   (SM_WH + 128 * STR)
#define SM_TOTAL (SM_WL + 128 * STR)

__global__ __launch_bounds__(256, 1) void k_fused_mma(
    const float* __restrict__ h, const float* __restrict__ b2f,
    const float* __restrict__ b3f, const float* __restrict__ b4f,
    const float* __restrict__ g1f, const float* __restrict__ be1f,
    const float* __restrict__ g2f, const float* __restrict__ be2f,
    float* __restrict__ out) {
    extern __shared__ char smc[];
    const int tid = threadIdx.x;
    const int warp = tid >> 5, lane = tid & 31;
    const int g = lane >> 2, t = lane & 3;
    const int row0 = blockIdx.x * 128;
    const int r0 = warp * 16;

    if (tid < 128) {
        int r = row0 + tid;
        ((float*)(smc + SM_CN))[tid]  = (r < NN) ? rsqrtf(fmaxf((float)g_degi_node[r], 1.f)) : 0.f;
        ((float*)(smc + SM_B2))[tid]  = b2f[tid];
        ((float*)(smc + SM_B4))[tid]  = b4f[tid];
        ((float*)(smc + SM_G1))[tid]  = g1f[tid];
        ((float*)(smc + SM_BE1))[tid] = be1f[tid];
        ((float*)(smc + SM_G2))[tid]  = g2f[tid];
        ((float*)(smc + SM_BE2))[tid] = be2f[tid];
    }
    for (int i = tid; i < 512; i += 256) ((float*)(smc + SM_B3))[i] = b3f[i];

#pragma unroll
    for (int i = tid; i < 4096; i += 256) {
        int r = i >> 5, c4 = (i & 31) * 4;
        float4 v = make_float4(0.f, 0.f, 0.f, 0.f);
        if (row0 + r < NN) v = *(const float4*)&g_node_acc[(row0 + r) * DD + c4];
        char* pH = smc + SM_A1H + r * STR + c4 * 2;
        char* pL = smc + SM_A1L + r * STR + c4 * 2;
        sts_hilo(pH, pL, v.x, v.y);
        sts_hilo(pH + 4, pL + 4, v.z, v.w);
    }
    stage_w(smc, SM_WH, SM_WL, g_w2t_h, g_w2t_l, 128);
    __syncthreads();

    const int gr0 = row0 + r0 + g, gr1 = gr0 + 8;
    const float cn0 = ((float*)(smc + SM_CN))[r0 + g];
    const float cn1 = ((float*)(smc + SM_CN))[r0 + g + 8];

    // ---- GEMM2 ----
    float dA[16][4];
#pragma unroll
    for (int j = 0; j < 16; j++)
#pragma unroll
        for (int p = 0; p < 4; p++) dA[j][p] = 0.f;
    gemm128(smc, SM_A1H, SM_A1L, SM_WH, SM_WL, r0, g, t, dA);

    // ---- epilogue: h1 = LN1(h + cn*D + b2) -> A1 planes ----
    {
        const float* b2s = (const float*)(smc + SM_B2);
        float s0 = 0.f, q0 = 0.f, s1 = 0.f, q1 = 0.f;
#pragma unroll
        for (int j = 0; j < 16; j++) {
            int c = 8 * j + 2 * t;
            float2 h0 = make_float2(0.f, 0.f), h1v = make_float2(0.f, 0.f);
            if (gr0 < NN) h0 = *(const float2*)&h[gr0 * DD + c];
            if (gr1 < NN) h1v = *(const float2*)&h[gr1 * DD + c];
            float x0 = h0.x + cn0 * dA[j][0] + b2s[c];
            float x1 = h0.y + cn0 * dA[j][1] + b2s[c + 1];
            float x2 = h1v.x + cn1 * dA[j][2] + b2s[c];
            float x3 = h1v.y + cn1 * dA[j][3] + b2s[c + 1];
            dA[j][0] = x0; dA[j][1] = x1; dA[j][2] = x2; dA[j][3] = x3;
            s0 += x0 + x1; q0 += x0 * x0 + x1 * x1;
            s1 += x2 + x3; q1 += x2 * x2 + x3 * x3;
        }
        s0 += __shfl_xor_sync(~0u, s0, 1); s0 += __shfl_xor_sync(~0u, s0, 2);
        q0 += __shfl_xor_sync(~0u, q0, 1); q0 += __shfl_xor_sync(~0u, q0, 2);
        s1 += __shfl_xor_sync(~0u, s1, 1); s1 += __shfl_xor_sync(~0u, s1, 2);
        q1 += __shfl_xor_sync(~0u, q1, 1); q1 += __shfl_xor_sync(~0u, q1, 2);
        float mu0 = s0 * (1.f / 128.f), mu1 = s1 * (1.f / 128.f);
        float inv0 = rsqrtf(fmaxf(q0 * (1.f / 128.f) - mu0 * mu0, 0.f) + 1e-5f);
        float inv1 = rsqrtf(fmaxf(q1 * (1.f / 128.f) - mu1 * mu1, 0.f) + 1e-5f);
        const float* g1s = (const float*)(smc + SM_G1);
        const float* be1s = (const float*)(smc + SM_BE1);
#pragma unroll
        for (int j = 0; j < 16; j++) {
            int c = 8 * j + 2 * t;
            float y0 = (dA[j][0] - mu0) * inv0 * g1s[c] + be1s[c];
            float y1 = (dA[j][1] - mu0) * inv0 * g1s[c + 1] + be1s[c + 1];
            float y2 = (dA[j][2] - mu1) * inv1 * g1s[c] + be1s[c];
            float y3 = (dA[j][3] - mu1) * inv1 * g1s[c + 1] + be1s[c + 1];
            char* pH = smc + SM_A1H + (r0 + g) * STR + c * 2;
            char* pL = smc + SM_A1L + (r0 + g) * STR + c * 2;
            sts_hilo(pH, pL, y0, y1);
            sts_hilo(pH + 8 * STR, pL + 8 * STR, y2, y3);
        }
    }

    // ---- FFN ----
    float dC[16][4];
#pragma unroll
    for (int j = 0; j < 16; j++)
#pragma unroll
        for (int p = 0; p < 4; p++) dC[j][p] = 0.f;

    for (int nc = 0; nc < 4; nc++) {
        __syncthreads();
        stage_w(smc, SM_WH, SM_WL, g_w3t_h + nc * 128 * DD, g_w3t_l + nc * 128 * DD, 128);
        __syncthreads();
        float dB[16][4];
#pragma unroll
        for (int j = 0; j < 16; j++)
#pragma unroll
            for (int p = 0; p < 4; p++) dB[j][p] = 0.f;
        gemm128(smc, SM_A1H, SM_A1L, SM_WH, SM_WL, r0, g, t, dB);
        const float* b3s = (const float*)(smc + SM_B3) + nc * 128;
#pragma unroll
        for (int j = 0; j < 16; j++) {
            int c = 8 * j + 2 * t;
            float x0 = fmaxf(dB[j][0] + b3s[c], 0.f);
            float x1 = fmaxf(dB[j][1] + b3s[c + 1], 0.f);
            float x2 = fmaxf(dB[j][2] + b3s[c], 0.f);
            float x3 = fmaxf(dB[j][3] + b3s[c + 1], 0.f);
            char* pH = smc + SM_A2H + (r0 + g) * STR + c * 2;
            char* pL = smc + SM_A2L + (r0 + g) * STR + c * 2;
            sts_hilo(pH, pL, x0, x1);
            sts_hilo(pH + 8 * STR, pL + 8 * STR, x2, x3);
        }
        __syncthreads();
        stage_w(smc, SM_WH, SM_WL, g_w4t_h + nc * 128, g_w4t_l + nc * 128, 512);
        __syncthreads();
        gemm128(smc, SM_A2H, SM_A2L, SM_WH, SM_WL, r0, g, t, dC);
    }

    // ---- final epilogue: LN2(D2 + b4 + h1) -> out ----
    {
        const float* b4s = (const float*)(smc + SM_B4);
        float s0 = 0.f, q0 = 0.f, s1 = 0.f, q1 = 0.f;
#pragma unroll
        for (int j = 0; j < 16; j++) {
            int c = 8 * j + 2 * t;
            const char* pH = smc + SM_A1H + (r0 + g) * STR + c * 2;
            const char* pL = smc + SM_A1L + (r0 + g) * STR + c * 2;
            __nv_bfloat162 hh0 = *(const __nv_bfloat162*)(pH);
            __nv_bfloat162 ll0 = *(const __nv_bfloat162*)(pL);
            __nv_bfloat162 hh1 = *(const __nv_bfloat162*)(pH + 8 * STR);
            __nv_bfloat162 ll1 = *(const __nv_bfloat162*)(pL + 8 * STR);
            float x0 = dC[j][0] + b4s[c] + __bfloat162float(hh0.x) + __bfloat162float(ll0.x);
            float x1 = dC[j][1] + b4s[c + 1] + __bfloat162float(hh0.y) + __bfloat162float(ll0.y);
            float x2 = dC[j][2] + b4s[c] + __bfloat162float(hh1.x) + __bfloat162float(ll1.x);
            float x3 = dC[j][3] + b4s[c + 1] + __bfloat162float(hh1.y) + __bfloat162float(ll1.y);
            dC[j][0] = x0; dC[j][1] = x1; dC[j][2] = x2; dC[j][3] = x3;
            s0 += x0 + x1; q0 += x0 * x0 + x1 * x1;
            s1 += x2 + x3; q1 += x2 * x2 + x3 * x3;
        }
        s0 += __shfl_xor_sync(~0u, s0, 1); s0 += __shfl_xor_sync(~0u, s0, 2);
        q0 += __shfl_xor_sync(~0u, q0, 1); q0 += __shfl_xor_sync(~0u, q0, 2);
        s1 += __shfl_xor_sync(~0u, s1, 1); s1 += __shfl_xor_sync(~0u, s1, 2);
        q1 += __shfl_xor_sync(~0u, q1, 1); q1 += __shfl_xor_sync(~0u, q1, 2);
        float mu0 = s0 * (1.f / 128.f), mu1 = s1 * (1.f / 128.f);
        float inv0 = rsqrtf(fmaxf(q0 * (1.f / 128.f) - mu0 * mu0, 0.f) + 1e-5f);
        float inv1 = rsqrtf(fmaxf(q1 * (1.f / 128.f) - mu1 * mu1, 0.f) + 1e-5f);
        const float* g2s = (const float*)(smc + SM_G2);
        const float* be2s = (const float*)(smc + SM_BE2);
#pragma unroll
        for (int j = 0; j < 16; j++) {
            int c = 8 * j + 2 * t;
            if (gr0 < NN) {
                float2 o;
                o.x = (dC[j][0] - mu0) * inv0 * g2s[c] + be2s[c];
                o.y = (dC[j][1] - mu0) * inv0 * g2s[c + 1] + be2s[c + 1];
                *(float2*)&out[gr0 * DD + c] = o;
            }
            if (gr1 < NN) {
                float2 o;
                o.x = (dC[j][2] - mu1) * inv1 * g2s[c] + be2s[c];
                o.y = (dC[j][3] - mu1) * inv1 * g2s[c + 1] + be2s[c + 1];
                *(float2*)&out[gr1 * DD + c] = o;
            }
        }
    }
}

// ---------------- launch ----------------
extern "C" void kernel_launch(void* const* d_in, const int* in_sizes, int n_in,
                              void* d_out, int out_size) {
    const float* h   = (const float*)d_in[0];
    const int*   src = (const int*)d_in[1];
    const int*   dst = (const int*)d_in[2];
    const float* W1  = (const float*)d_in[3];
    const float* b1  = (const float*)d_in[4];
    const float* W2  = (const float*)d_in[5];
    const float* b2  = (const float*)d_in[6];
    const float* W3  = (const float*)d_in[7];
    const float* b3  = (const float*)d_in[8];
    const float* W4  = (const float*)d_in[9];
    const float* b4  = (const float*)d_in[10];
    const float* g1  = (const float*)d_in[11];
    const float* be1 = (const float*)d_in[12];
    const float* g2  = (const float*)d_in[13];
    const float* be2 = (const float*)d_in[14];
    float* out = (float*)d_out;

    cudaFuncSetAttribute(k_gemm1_mma, cudaFuncAttributeMaxDynamicSharedMemorySize, SM1_TOTAL);
    cudaFuncSetAttribute(k_fused_mma, cudaFuncAttributeMaxDynamicSharedMemorySize, SM_TOTAL);

    k_zero<<<512, 256>>>();
    k_wconv<<<288, 256>>>(W1, W2, W3, W4);
    k_deg<<<(NE + 255) / 256, 256>>>(src, dst);
    k_scan<<<1, 1024>>>(0);   // hyperedge offsets
    k_scan<<<1, 1024>>>(1);   // node offsets
    k_place<<<(NE + 255) / 256, 256>>>(src, dst);
    k_scale_h<<<(NN * 32 + 255) / 256, 256>>>(h);
    k_gather1<<<(NH * 32 + 255) / 256, 256>>>();
    k_gemm1_mma<<<(NH + 127) / 128, 256, SM1_TOTAL>>>(b1);
    k_gather2<<<(NN * 32 + 255) / 256, 256>>>();
    k_fused_mma<<<(NN + 127) / 128, 256, SM_TOTAL>>>(h, b2, b3, b4,
                                                     g1, be1, g2, be2, out);
}

// round 8
// speedup vs baseline: 1.8983x; 1.0527x over previous
#include <cuda_runtime.h>
#include <cuda_bf16.h>
#include <cstdint>

#define NN 100000
#define NH 20000
#define NE 1600000
#define DD 128
#define HH 512

// ---------------- scratch (device globals; no allocation allowed) ----------------
__device__ __align__(16) int g_degi_node[NN];
__device__ __align__(16) int g_degi_he[NH];
__device__ __align__(16) int g_off_node[NN + 1];
__device__ __align__(16) int g_off_he[NH + 1];
__device__ __align__(16) int g_cur_node[NN];
__device__ __align__(16) int g_cur_he[NH];
__device__ __align__(16) int g_srt_src[NE];     // edges sorted by dst -> src ids
__device__ __align__(16) int g_srt_dst[NE];     // edges sorted by src -> dst ids
__device__ __align__(16) float g_hyper_acc[NH * DD];
__device__ __align__(16) float g_hyper_msg[NH * DD];
__device__ __align__(16) float g_node_acc[NN * DD];
// pre-transposed bf16 hi/lo weight planes: [n][k] layout
__device__ __align__(16) __nv_bfloat16 g_w1t_h[DD * DD];
__device__ __align__(16) __nv_bfloat16 g_w1t_l[DD * DD];
__device__ __align__(16) __nv_bfloat16 g_w2t_h[DD * DD];
__device__ __align__(16) __nv_bfloat16 g_w2t_l[DD * DD];
__device__ __align__(16) __nv_bfloat16 g_w3t_h[HH * DD];   // [n=0..511][k=0..127]
__device__ __align__(16) __nv_bfloat16 g_w3t_l[HH * DD];
__device__ __align__(16) __nv_bfloat16 g_w4t_h[DD * HH];   // [n=0..127][kk=0..511]
__device__ __align__(16) __nv_bfloat16 g_w4t_l[DD * HH];

// =================== preprocessing kernels ===================
__global__ void k_zero() {
    int idx = blockIdx.x * blockDim.x + threadIdx.x;
    int nthr = gridDim.x * blockDim.x;
    for (int i = idx; i < NN; i += nthr) { g_degi_node[i] = 0; g_cur_node[i] = 0; }
    for (int i = idx; i < NH; i += nthr) { g_degi_he[i] = 0; g_cur_he[i] = 0; }
}

__global__ void k_deg(const int* __restrict__ src, const int* __restrict__ dst) {
    int e = blockIdx.x * blockDim.x + threadIdx.x;
    if (e < NE) {
        atomicAdd(&g_degi_node[src[e]], 1);
        atomicAdd(&g_degi_he[dst[e]], 1);
    }
}

// two independent single-block exclusive scans (block 0: hyperedges, block 1: nodes).
// device globals referenced from device code only (host-arg shadow + ATS trap).
__global__ void k_scan2() {
    const int which = blockIdx.x;
    const int* __restrict__ cnt = which ? g_degi_node : g_degi_he;
    int* __restrict__ off = which ? g_off_node : g_off_he;
    const int n = which ? NN : NH;
    __shared__ int sh[1024];
    int tid = threadIdx.x;
    int chunk = (n + 1023) >> 10;
    int b = tid * chunk, e = b + chunk;
    if (b > n) b = n;
    if (e > n) e = n;
    int s = 0;
    for (int i = b; i < e; i++) s += cnt[i];
    sh[tid] = s;
    __syncthreads();
    for (int o = 1; o < 1024; o <<= 1) {
        int t = (tid >= o) ? sh[tid - o] : 0;
        __syncthreads();
        sh[tid] += t;
        __syncthreads();
    }
    int run = sh[tid] - s;
    for (int i = b; i < e; i++) { off[i] = run; run += cnt[i]; }
    if (tid == 1023) off[n] = sh[1023];
}

__global__ void k_place(const int* __restrict__ src, const int* __restrict__ dst) {
    int e = blockIdx.x * blockDim.x + threadIdx.x;
    if (e < NE) {
        int s = src[e], d = dst[e];
        int p1 = g_off_he[d] + atomicAdd(&g_cur_he[d], 1);
        g_srt_src[p1] = s;
        int p2 = g_off_node[s] + atomicAdd(&g_cur_node[s], 1);
        g_srt_dst[p2] = d;
    }
}

// weight transpose + bf16 hi/lo precompute (once per launch)
__global__ void k_wconv(const float* __restrict__ W1, const float* __restrict__ W2,
                        const float* __restrict__ W3, const float* __restrict__ W4) {
    int idx0 = blockIdx.x * blockDim.x + threadIdx.x;
    int nt = gridDim.x * blockDim.x;
    for (int i = idx0; i < DD * DD; i += nt) {
        int n = i >> 7, k = i & 127;
        float v = W1[k * DD + n];
        __nv_bfloat16 hi = __float2bfloat16(v);
        g_w1t_h[i] = hi;
        g_w1t_l[i] = __float2bfloat16(v - __bfloat162float(hi));
        float v2 = W2[k * DD + n];
        __nv_bfloat16 hi2 = __float2bfloat16(v2);
        g_w2t_h[i] = hi2;
        g_w2t_l[i] = __float2bfloat16(v2 - __bfloat162float(hi2));
    }
    for (int i = idx0; i < HH * DD; i += nt) {
        int n = i >> 7, k = i & 127;
        float v = W3[k * HH + n];
        __nv_bfloat16 hi = __float2bfloat16(v);
        g_w3t_h[i] = hi;
        g_w3t_l[i] = __float2bfloat16(v - __bfloat162float(hi));
    }
    for (int i = idx0; i < DD * HH; i += nt) {
        int n = i >> 9, kk = i & 511;
        float v = W4[kk * DD + n];
        __nv_bfloat16 hi = __float2bfloat16(v);
        g_w4t_h[i] = hi;
        g_w4t_l[i] = __float2bfloat16(v - __bfloat162float(hi));
    }
}

// =================== segmented gathers (no atomics) ===================
// warp per hyperedge: hyper_acc[he] = sum over edges of cn[src]*h[src]
__global__ void k_gather1(const float* __restrict__ h) {
    int w = (blockIdx.x * blockDim.x + threadIdx.x) >> 5;
    if (w >= NH) return;
    int lane = threadIdx.x & 31;
    int beg = g_off_he[w], end = g_off_he[w + 1];
    float4 acc = make_float4(0.f, 0.f, 0.f, 0.f);
    for (int e = beg; e < end; e += 32) {
        int n = end - e;
        if (n > 32) n = 32;
        int idx = g_srt_src[e + (lane < n ? lane : 0)];
        float cnl = rsqrtf(fmaxf((float)g_degi_node[idx], 1.f));
#pragma unroll 4
        for (int j = 0; j < n; j++) {
            int s = __shfl_sync(0xffffffffu, idx, j);
            float c = __shfl_sync(0xffffffffu, cnl, j);
            float4 v = __ldg(&((const float4*)h)[s * 32 + lane]);
            acc.x = fmaf(c, v.x, acc.x);
            acc.y = fmaf(c, v.y, acc.y);
            acc.z = fmaf(c, v.z, acc.z);
            acc.w = fmaf(c, v.w, acc.w);
        }
    }
    ((float4*)g_hyper_acc)[w * 32 + lane] = acc;
}

// warp per node: node_acc[nd] = sum over edges of hyper_msg[dst]
__global__ void k_gather2() {
    int w = (blockIdx.x * blockDim.x + threadIdx.x) >> 5;
    if (w >= NN) return;
    int lane = threadIdx.x & 31;
    int beg = g_off_node[w], end = g_off_node[w + 1];
    float4 acc = make_float4(0.f, 0.f, 0.f, 0.f);
    for (int e = beg; e < end; e += 32) {
        int n = end - e;
        if (n > 32) n = 32;
        int idx = g_srt_dst[e + (lane < n ? lane : 0)];
#pragma unroll 4
        for (int j = 0; j < n; j++) {
            int d = __shfl_sync(0xffffffffu, idx, j);
            float4 v = __ldg(&((const float4*)g_hyper_msg)[d * 32 + lane]);
            acc.x += v.x; acc.y += v.y; acc.z += v.z; acc.w += v.w;
        }
    }
    ((float4*)g_node_acc)[w * 32 + lane] = acc;
}

// =================== HMMA machinery ===================
#define STR 272

__device__ __forceinline__ void mma_bf16(float d[4], uint32_t a0, uint32_t a1,
                                         uint32_t a2, uint32_t a3,
                                         uint32_t b0, uint32_t b1) {
    asm volatile(
        "mma.sync.aligned.m16n8k16.row.col.f32.bf16.bf16.f32 "
        "{%0,%1,%2,%3}, {%4,%5,%6,%7}, {%8,%9}, {%0,%1,%2,%3};"
        : "+f"(d[0]), "+f"(d[1]), "+f"(d[2]), "+f"(d[3])
        : "r"(a0), "r"(a1), "r"(a2), "r"(a3), "r"(b0), "r"(b1));
}

__device__ __forceinline__ void sts_hilo(char* pH, char* pL, float x0, float x1) {
    __nv_bfloat16 h0 = __float2bfloat16(x0), h1 = __float2bfloat16(x1);
    float r0f = x0 - __bfloat162float(h0), r1f = x1 - __bfloat162float(h1);
    *(__nv_bfloat162*)pH = __halves2bfloat162(h0, h1);
    *(__nv_bfloat162*)pL = __halves2bfloat162(__float2bfloat16(r0f), __float2bfloat16(r1f));
}

// D[32 warp-rows x 64 warp-cols] += A[32x128] @ W^T[64x128], 3-term hi/lo.
// Warp tile: rows R0..R0+31 (2 m16 tiles), cols C0..C0+63 (8 n8 tiles).
__device__ __forceinline__ void gemm32x64(const char* smc, int aHoff, int aLoff,
                                          int wHoff, int wLoff,
                                          int R0, int C0, int g, int t,
                                          float d[2][8][4]) {
    const char* pAH = smc + aHoff + (R0 + g) * STR + t * 4;
    const char* pAL = smc + aLoff + (R0 + g) * STR + t * 4;
    const char* pBH = smc + wHoff + (C0 + g) * STR + t * 4;
    const char* pBL = smc + wLoff + (C0 + g) * STR + t * 4;
#pragma unroll 2
    for (int k = 0; k < 8; k++) {
        uint32_t ah[2][4], al[2][4];
#pragma unroll
        for (int i = 0; i < 2; i++) {
            const char* pH = pAH + i * 16 * STR;
            const char* pL = pAL + i * 16 * STR;
            ah[i][0] = *(const uint32_t*)(pH);
            ah[i][1] = *(const uint32_t*)(pH + 8 * STR);
            ah[i][2] = *(const uint32_t*)(pH + 16);
            ah[i][3] = *(const uint32_t*)(pH + 8 * STR + 16);
            al[i][0] = *(const uint32_t*)(pL);
            al[i][1] = *(const uint32_t*)(pL + 8 * STR);
            al[i][2] = *(const uint32_t*)(pL + 16);
            al[i][3] = *(const uint32_t*)(pL + 8 * STR + 16);
        }
#pragma unroll
        for (int j = 0; j < 8; j++) {
            const char* bH = pBH + j * 8 * STR;
            const char* bL = pBL + j * 8 * STR;
            uint32_t bh0 = *(const uint32_t*)(bH);
            uint32_t bh1 = *(const uint32_t*)(bH + 16);
            uint32_t bl0 = *(const uint32_t*)(bL);
            uint32_t bl1 = *(const uint32_t*)(bL + 16);
#pragma unroll
            for (int i = 0; i < 2; i++) {
                mma_bf16(d[i][j], ah[i][0], ah[i][1], ah[i][2], ah[i][3], bh0, bh1);
                mma_bf16(d[i][j], al[i][0], al[i][1], al[i][2], al[i][3], bh0, bh1);
                mma_bf16(d[i][j], ah[i][0], ah[i][1], ah[i][2], ah[i][3], bl0, bl1);
            }
        }
        pAH += 32; pAL += 32; pBH += 32; pBL += 32;
    }
}

__device__ __forceinline__ void stage_w(char* smc, int wHoff, int wLoff,
                                        const __nv_bfloat16* srcH,
                                        const __nv_bfloat16* srcL, int srcStride) {
    int tid = threadIdx.x;
#pragma unroll
    for (int i = tid; i < 2048; i += 256) {
        int r = i >> 4, c8 = (i & 15) * 8;
        uint4 vh = *(const uint4*)(srcH + r * srcStride + c8);
        uint4 vl = *(const uint4*)(srcL + r * srcStride + c8);
        *(uint4*)(smc + wHoff + r * STR + c8 * 2) = vh;
        *(uint4*)(smc + wLoff + r * STR + c8 * 2) = vl;
    }
}

// ---- GEMM1 (hyper): g_hyper_msg = ch^2*(hyper_acc @ W1) + ch*b1 ----
#define SM1_CH 0
#define SM1_B1 512
#define SM1_AH 1024
#define SM1_AL (SM1_AH + 128 * STR)
#define SM1_WH (SM1_AL + 128 * STR)
#define SM1_WL (SM1_WH + 128 * STR)
#define SM1_TOTAL (SM1_WL + 128 * STR)

__global__ __launch_bounds__(256, 1) void k_gemm1_mma(const float* __restrict__ b1f) {
    extern __shared__ char smc[];
    const int tid = threadIdx.x;
    const int warp = tid >> 5, lane = tid & 31;
    const int g = lane >> 2, t = lane & 3;
    const int mg = warp & 3, ng = warp >> 2;
    const int R0 = mg * 32, C0 = ng * 64;
    const int row0 = blockIdx.x * 128;

    if (tid < 128) {
        int r = row0 + tid;
        ((float*)(smc + SM1_CH))[tid] = (r < NH) ? rsqrtf(fmaxf((float)g_degi_he[r], 1.f)) : 0.f;
        ((float*)(smc + SM1_B1))[tid] = b1f[tid];
    }
#pragma unroll
    for (int i = tid; i < 4096; i += 256) {
        int r = i >> 5, c4 = (i & 31) * 4;
        float4 v = make_float4(0.f, 0.f, 0.f, 0.f);
        if (row0 + r < NH) v = *(const float4*)&g_hyper_acc[(row0 + r) * DD + c4];
        char* pH = smc + SM1_AH + r * STR + c4 * 2;
        char* pL = smc + SM1_AL + r * STR + c4 * 2;
        sts_hilo(pH, pL, v.x, v.y);
        sts_hilo(pH + 4, pL + 4, v.z, v.w);
    }
    stage_w(smc, SM1_WH, SM1_WL, g_w1t_h, g_w1t_l, 128);
    __syncthreads();

    float dA[2][8][4];
#pragma unroll
    for (int i = 0; i < 2; i++)
#pragma unroll
        for (int j = 0; j < 8; j++)
#pragma unroll
            for (int p = 0; p < 4; p++) dA[i][j][p] = 0.f;
    gemm32x64(smc, SM1_AH, SM1_AL, SM1_WH, SM1_WL, R0, C0, g, t, dA);

    const float* b1s = (const float*)(smc + SM1_B1);
    const float* chs = (const float*)(smc + SM1_CH);
#pragma unroll
    for (int i = 0; i < 2; i++)
#pragma unroll
        for (int hh = 0; hh < 2; hh++) {
            int row = R0 + i * 16 + hh * 8 + g;
            int gr = row0 + row;
            if (gr >= NH) continue;
            float ch = chs[row];
            float chq = ch * ch;
#pragma unroll
            for (int j = 0; j < 8; j++) {
                int c = C0 + j * 8 + t * 2;
                float2 o;
                o.x = dA[i][j][hh * 2] * chq + b1s[c] * ch;
                o.y = dA[i][j][hh * 2 + 1] * chq + b1s[c + 1] * ch;
                *(float2*)&g_hyper_msg[gr * DD + c] = o;
            }
        }
}

// ---- fused GEMM2 + LN1 + FFN + LN2 ----
#define SM_CN   0
#define SM_B2   512
#define SM_B4   1024
#define SM_G1   1536
#define SM_BE1  2048
#define SM_G2   2560
#define SM_BE2  3072
#define SM_B3   3584
#define SM_SUM  5632
#define SM_SQ   6656
#define SM_A1H  7680
#define SM_A1L  (SM_A1H + 128 * STR)
#define SM_A2H  (SM_A1L + 128 * STR)
#define SM_A2L  (SM_A2H + 128 * STR)
#define SM_WH   (SM_A2L + 128 * STR)
#define SM_WL   (SM_WH + 128 * STR)
#define SM_TOTAL (SM_WL + 128 * STR)

__global__ __launch_bounds__(256, 1) void k_fused_mma(
    const float* __restrict__ h, const float* __restrict__ b2f,
    const float* __restrict__ b3f, const float* __restrict__ b4f,
    const float* __restrict__ g1f, const float* __restrict__ be1f,
    const float* __restrict__ g2f, const float* __restrict__ be2f,
    float* __restrict__ out) {
    extern __shared__ char smc[];
    const int tid = threadIdx.x;
    const int warp = tid >> 5, lane = tid & 31;
    const int g = lane >> 2, t = lane & 3;
    const int mg = warp & 3, ng = warp >> 2;
    const int R0 = mg * 32, C0 = ng * 64;
    const int row0 = blockIdx.x * 128;

    if (tid < 128) {
        int r = row0 + tid;
        ((float*)(smc + SM_CN))[tid]  = (r < NN) ? rsqrtf(fmaxf((float)g_degi_node[r], 1.f)) : 0.f;
        ((float*)(smc + SM_B2))[tid]  = b2f[tid];
        ((float*)(smc + SM_B4))[tid]  = b4f[tid];
        ((float*)(smc + SM_G1))[tid]  = g1f[tid];
        ((float*)(smc + SM_BE1))[tid] = be1f[tid];
        ((float*)(smc + SM_G2))[tid]  = g2f[tid];
        ((float*)(smc + SM_BE2))[tid] = be2f[tid];
    }
    for (int i = tid; i < 512; i += 256) ((float*)(smc + SM_B3))[i] = b3f[i];

#pragma unroll
    for (int i = tid; i < 4096; i += 256) {
        int r = i >> 5, c4 = (i & 31) * 4;
        float4 v = make_float4(0.f, 0.f, 0.f, 0.f);
        if (row0 + r < NN) v = *(const float4*)&g_node_acc[(row0 + r) * DD + c4];
        char* pH = smc + SM_A1H + r * STR + c4 * 2;
        char* pL = smc + SM_A1L + r * STR + c4 * 2;
        sts_hilo(pH, pL, v.x, v.y);
        sts_hilo(pH + 4, pL + 4, v.z, v.w);
    }
    stage_w(smc, SM_WH, SM_WL, g_w2t_h, g_w2t_l, 128);
    __syncthreads();

    const float* cns = (const float*)(smc + SM_CN);
    float* sums = (float*)(smc + SM_SUM);   // [2][128]
    float* sqs  = (float*)(smc + SM_SQ);

    // ---- GEMM2 ----
    float dA[2][8][4];
#pragma unroll
    for (int i = 0; i < 2; i++)
#pragma unroll
        for (int j = 0; j < 8; j++)
#pragma unroll
            for (int p = 0; p < 4; p++) dA[i][j][p] = 0.f;
    gemm32x64(smc, SM_A1H, SM_A1L, SM_WH, SM_WL, R0, C0, g, t, dA);

    // ---- epilogue: h1 = LN1(h + cn*D + b2) -> A1 planes ----
    {
        const float* b2s = (const float*)(smc + SM_B2);
        float rs[2][2], rq[2][2];
#pragma unroll
        for (int i = 0; i < 2; i++)
#pragma unroll
            for (int hh = 0; hh < 2; hh++) {
                int row = R0 + i * 16 + hh * 8 + g;
                int grow = row0 + row;
                float cn = cns[row];
                float s = 0.f, q = 0.f;
#pragma unroll
                for (int j = 0; j < 8; j++) {
                    int c = C0 + j * 8 + t * 2;
                    float2 hv = make_float2(0.f, 0.f);
                    if (grow < NN) hv = *(const float2*)&h[grow * DD + c];
                    float x0 = hv.x + cn * dA[i][j][hh * 2] + b2s[c];
                    float x1 = hv.y + cn * dA[i][j][hh * 2 + 1] + b2s[c + 1];
                    dA[i][j][hh * 2] = x0;
                    dA[i][j][hh * 2 + 1] = x1;
                    s += x0 + x1;
                    q += x0 * x0 + x1 * x1;
                }
                rs[i][hh] = s; rq[i][hh] = q;
            }
#pragma unroll
        for (int i = 0; i < 2; i++)
#pragma unroll
            for (int hh = 0; hh < 2; hh++) {
                rs[i][hh] += __shfl_xor_sync(~0u, rs[i][hh], 1);
                rs[i][hh] += __shfl_xor_sync(~0u, rs[i][hh], 2);
                rq[i][hh] += __shfl_xor_sync(~0u, rq[i][hh], 1);
                rq[i][hh] += __shfl_xor_sync(~0u, rq[i][hh], 2);
            }
        if (t == 0) {
#pragma unroll
            for (int i = 0; i < 2; i++)
#pragma unroll
                for (int hh = 0; hh < 2; hh++) {
                    int row = R0 + i * 16 + hh * 8 + g;
                    sums[ng * 128 + row] = rs[i][hh];
                    sqs[ng * 128 + row] = rq[i][hh];
                }
        }
        __syncthreads();
        const float* g1s = (const float*)(smc + SM_G1);
        const float* be1s = (const float*)(smc + SM_BE1);
#pragma unroll
        for (int i = 0; i < 2; i++)
#pragma unroll
            for (int hh = 0; hh < 2; hh++) {
                int row = R0 + i * 16 + hh * 8 + g;
                float ts = sums[row] + sums[128 + row];
                float tq = sqs[row] + sqs[128 + row];
                float mu = ts * (1.f / 128.f);
                float inv = rsqrtf(fmaxf(tq * (1.f / 128.f) - mu * mu, 0.f) + 1e-5f);
#pragma unroll
                for (int j = 0; j < 8; j++) {
                    int c = C0 + j * 8 + t * 2;
                    float y0 = (dA[i][j][hh * 2] - mu) * inv * g1s[c] + be1s[c];
                    float y1 = (dA[i][j][hh * 2 + 1] - mu) * inv * g1s[c + 1] + be1s[c + 1];
                    sts_hilo(smc + SM_A1H + row * STR + c * 2,
                             smc + SM_A1L + row * STR + c * 2, y0, y1);
                }
            }
    }

    // ---- FFN ----
    float dC[2][8][4];
#pragma unroll
    for (int i = 0; i < 2; i++)
#pragma unroll
        for (int j = 0; j < 8; j++)
#pragma unroll
            for (int p = 0; p < 4; p++) dC[i][j][p] = 0.f;

    for (int nc = 0; nc < 4; nc++) {
        __syncthreads();
        stage_w(smc, SM_WH, SM_WL, g_w3t_h + nc * 128 * DD, g_w3t_l + nc * 128 * DD, 128);
        __syncthreads();
        float dB[2][8][4];
#pragma unroll
        for (int i = 0; i < 2; i++)
#pragma unroll
            for (int j = 0; j < 8; j++)
#pragma unroll
                for (int p = 0; p < 4; p++) dB[i][j][p] = 0.f;
        gemm32x64(smc, SM_A1H, SM_A1L, SM_WH, SM_WL, R0, C0, g, t, dB);
        const float* b3s = (const float*)(smc + SM_B3) + nc * 128;
#pragma unroll
        for (int i = 0; i < 2; i++)
#pragma unroll
            for (int hh = 0; hh < 2; hh++) {
                int row = R0 + i * 16 + hh * 8 + g;
#pragma unroll
                for (int j = 0; j < 8; j++) {
                    int c = C0 + j * 8 + t * 2;
                    float x0 = fmaxf(dB[i][j][hh * 2] + b3s[c], 0.f);
                    float x1 = fmaxf(dB[i][j][hh * 2 + 1] + b3s[c + 1], 0.f);
                    sts_hilo(smc + SM_A2H + row * STR + c * 2,
                             smc + SM_A2L + row * STR + c * 2, x0, x1);
                }
            }
        __syncthreads();
        stage_w(smc, SM_WH, SM_WL, g_w4t_h + nc * 128, g_w4t_l + nc * 128, 512);
        __syncthreads();
        gemm32x64(smc, SM_A2H, SM_A2L, SM_WH, SM_WL, R0, C0, g, t, dC);
    }

    // ---- final epilogue: LN2(D2 + b4 + h1) -> out ----
    {
        const float* b4s = (const float*)(smc + SM_B4);
        float rs[2][2], rq[2][2];
#pragma unroll
        for (int i = 0; i < 2; i++)
#pragma unroll
            for (int hh = 0; hh < 2; hh++) {
                int row = R0 + i * 16 + hh * 8 + g;
                float s = 0.f, q = 0.f;
#pragma unroll
                for (int j = 0; j < 8; j++) {
                    int c = C0 + j * 8 + t * 2;
                    const char* pH = smc + SM_A1H + row * STR + c * 2;
                    const char* pL = smc + SM_A1L + row * STR + c * 2;
                    __nv_bfloat162 hh2 = *(const __nv_bfloat162*)(pH);
                    __nv_bfloat162 ll2 = *(const __nv_bfloat162*)(pL);
                    float x0 = dC[i][j][hh * 2] + b4s[c]
                             + __bfloat162float(hh2.x) + __bfloat162float(ll2.x);
                    float x1 = dC[i][j][hh * 2 + 1] + b4s[c + 1]
                             + __bfloat162float(hh2.y) + __bfloat162float(ll2.y);
                    dC[i][j][hh * 2] = x0;
                    dC[i][j][hh * 2 + 1] = x1;
                    s += x0 + x1;
                    q += x0 * x0 + x1 * x1;
                }
                rs[i][hh] = s; rq[i][hh] = q;
            }
#pragma unroll
        for (int i = 0; i < 2; i++)
#pragma unroll
            for (int hh = 0; hh < 2; hh++) {
                rs[i][hh] += __shfl_xor_sync(~0u, rs[i][hh], 1);
                rs[i][hh] += __shfl_xor_sync(~0u, rs[i][hh], 2);
                rq[i][hh] += __shfl_xor_sync(~0u, rq[i][hh], 1);
                rq[i][hh] += __shfl_xor_sync(~0u, rq[i][hh], 2);
            }
        if (t == 0) {
#pragma unroll
            for (int i = 0; i < 2; i++)
#pragma unroll
                for (int hh = 0; hh < 2; hh++) {
                    int row = R0 + i * 16 + hh * 8 + g;
                    sums[ng * 128 + row] = rs[i][hh];
                    sqs[ng * 128 + row] = rq[i][hh];
                }
        }
        __syncthreads();
        const float* g2s = (const float*)(smc + SM_G2);
        const float* be2s = (const float*)(smc + SM_BE2);
#pragma unroll
        for (int i = 0; i < 2; i++)
#pragma unroll
            for (int hh = 0; hh < 2; hh++) {
                int row = R0 + i * 16 + hh * 8 + g;
                int grow = row0 + row;
                float ts = sums[row] + sums[128 + row];
                float tq = sqs[row] + sqs[128 + row];
                float mu = ts * (1.f / 128.f);
                float inv = rsqrtf(fmaxf(tq * (1.f / 128.f) - mu * mu, 0.f) + 1e-5f);
                if (grow < NN) {
#pragma unroll
                    for (int j = 0; j < 8; j++) {
                        int c = C0 + j * 8 + t * 2;
                        float2 o;
                        o.x = (dC[i][j][hh * 2] - mu) * inv * g2s[c] + be2s[c];
                        o.y = (dC[i][j][hh * 2 + 1] - mu) * inv * g2s[c + 1] + be2s[c + 1];
                        *(float2*)&out[grow * DD + c] = o;
                    }
                }
            }
    }
}

// ---------------- launch ----------------
extern "C" void kernel_launch(void* const* d_in, const int* in_sizes, int n_in,
                              void* d_out, int out_size) {
    const float* h   = (const float*)d_in[0];
    const int*   src = (const int*)d_in[1];
    const int*   dst = (const int*)d_in[2];
    const float* W1  = (const float*)d_in[3];
    const float* b1  = (const float*)d_in[4];
    const float* W2  = (const float*)d_in[5];
    const float* b2  = (const float*)d_in[6];
    const float* W3  = (const float*)d_in[7];
    const float* b3  = (const float*)d_in[8];
    const float* W4  = (const float*)d_in[9];
    const float* b4  = (const float*)d_in[10];
    const float* g1  = (const float*)d_in[11];
    const float* be1 = (const float*)d_in[12];
    const float* g2  = (const float*)d_in[13];
    const float* be2 = (const float*)d_in[14];
    float* out = (float*)d_out;

    cudaFuncSetAttribute(k_gemm1_mma, cudaFuncAttributeMaxDynamicSharedMemorySize, SM1_TOTAL);
    cudaFuncSetAttribute(k_fused_mma, cudaFuncAttributeMaxDynamicSharedMemorySize, SM_TOTAL);

    k_zero<<<512, 256>>>();
    k_wconv<<<288, 256>>>(W1, W2, W3, W4);
    k_deg<<<(NE + 255) / 256, 256>>>(src, dst);
    k_scan2<<<2, 1024>>>();
    k_place<<<(NE + 255) / 256, 256>>>(src, dst);
    k_gather1<<<(NH * 32 + 255) / 256, 256>>>(h);
    k_gemm1_mma<<<(NH + 127) / 128, 256, SM1_TOTAL>>>(b1);
    k_gather2<<<(NN * 32 + 255) / 256, 256>>>();
    k_fused_mma<<<(NN + 127) / 128, 256, SM_TOTAL>>>(h, b2, b3, b4,
                                                     g1, be1, g2, be2, out);
}

// round 9
// speedup vs baseline: 2.2109x; 1.1647x over previous
#include <cuda_runtime.h>
#include <cuda_bf16.h>
#include <cstdint>

#define NN 100000
#define NH 20000
#define NE 1600000
#define DD 128
#define HH 512

#define NB_HE 20      // ceil(NH/1024)
#define NB_NODE 98    // ceil(NN/1024)

// ---------------- scratch (device globals; no allocation allowed) ----------------
__device__ __align__(16) int g_degi_node[NN];
__device__ __align__(16) int g_degi_he[NH];
__device__ __align__(16) int g_off_node[NN + 1];
__device__ __align__(16) int g_off_he[NH + 1];
__device__ __align__(16) int g_cur_node[NN];
__device__ __align__(16) int g_cur_he[NH];
__device__ __align__(16) int g_bsum[NB_HE + NB_NODE];
__device__ __align__(16) int g_srt_src[NE];     // edges sorted by dst -> src ids
__device__ __align__(16) int g_srt_dst[NE];     // edges sorted by src -> dst ids
__device__ __align__(16) float g_hyper_acc[NH * DD];
__device__ __align__(16) float g_hyper_msg[NH * DD];
__device__ __align__(16) float g_node_acc[NN * DD];
// pre-transposed bf16 hi/lo weight planes: [n][k] layout
__device__ __align__(16) __nv_bfloat16 g_w1t_h[DD * DD];
__device__ __align__(16) __nv_bfloat16 g_w1t_l[DD * DD];
__device__ __align__(16) __nv_bfloat16 g_w2t_h[DD * DD];
__device__ __align__(16) __nv_bfloat16 g_w2t_l[DD * DD];
__device__ __align__(16) __nv_bfloat16 g_w3t_h[HH * DD];   // [n=0..511][k=0..127]
__device__ __align__(16) __nv_bfloat16 g_w3t_l[HH * DD];
__device__ __align__(16) __nv_bfloat16 g_w4t_h[DD * HH];   // [n=0..127][kk=0..511]
__device__ __align__(16) __nv_bfloat16 g_w4t_l[DD * HH];

// =================== preprocessing kernels ===================
__global__ void k_zero() {
    int idx = blockIdx.x * blockDim.x + threadIdx.x;
    int nthr = gridDim.x * blockDim.x;
    for (int i = idx; i < NN; i += nthr) { g_degi_node[i] = 0; g_cur_node[i] = 0; }
    for (int i = idx; i < NH; i += nthr) { g_degi_he[i] = 0; g_cur_he[i] = 0; }
}

__global__ void k_deg(const int* __restrict__ src, const int* __restrict__ dst) {
    int e = blockIdx.x * blockDim.x + threadIdx.x;
    if (e < NE) {
        atomicAdd(&g_degi_node[src[e]], 1);
        atomicAdd(&g_degi_he[dst[e]], 1);
    }
}

// ---- 3-pass multi-block exclusive scan (blocks 0..NB_HE-1: he, rest: node) ----
__global__ void k_scan_p1() {
    int b = blockIdx.x;
    const int* __restrict__ cnt;
    int* __restrict__ off;
    int n, lb;
    if (b < NB_HE) { cnt = g_degi_he; off = g_off_he; n = NH; lb = b; }
    else           { cnt = g_degi_node; off = g_off_node; n = NN; lb = b - NB_HE; }
    __shared__ int sh[1024];
    int tid = threadIdx.x;
    int i = lb * 1024 + tid;
    int v = (i < n) ? cnt[i] : 0;
    sh[tid] = v;
    __syncthreads();
    for (int o = 1; o < 1024; o <<= 1) {
        int t = (tid >= o) ? sh[tid - o] : 0;
        __syncthreads();
        sh[tid] += t;
        __syncthreads();
    }
    if (i < n) off[i] = sh[tid] - v;
    if (tid == 1023) g_bsum[b] = sh[1023];
}

__global__ void k_scan_p2() {
    if (threadIdx.x == 0) {
        int run = 0;
        for (int i = 0; i < NB_HE; i++) { int t = g_bsum[i]; g_bsum[i] = run; run += t; }
        g_off_he[NH] = run;
    }
    if (threadIdx.x == 1) {
        int run = 0;
        for (int i = NB_HE; i < NB_HE + NB_NODE; i++) { int t = g_bsum[i]; g_bsum[i] = run; run += t; }
        g_off_node[NN] = run;
    }
}

__global__ void k_scan_p3() {
    int b = blockIdx.x;
    int* __restrict__ off;
    int n, lb;
    if (b < NB_HE) { off = g_off_he; n = NH; lb = b; }
    else           { off = g_off_node; n = NN; lb = b - NB_HE; }
    int add = g_bsum[b];
    int i = lb * 1024 + threadIdx.x;
    if (i < n) off[i] += add;
}

__global__ void k_place(const int* __restrict__ src, const int* __restrict__ dst) {
    int e = blockIdx.x * blockDim.x + threadIdx.x;
    if (e < NE) {
        int s = src[e], d = dst[e];
        int p1 = g_off_he[d] + atomicAdd(&g_cur_he[d], 1);
        g_srt_src[p1] = s;
        int p2 = g_off_node[s] + atomicAdd(&g_cur_node[s], 1);
        g_srt_dst[p2] = d;
    }
}

// weight transpose + bf16 hi/lo precompute (once per launch)
__global__ void k_wconv(const float* __restrict__ W1, const float* __restrict__ W2,
                        const float* __restrict__ W3, const float* __restrict__ W4) {
    int idx0 = blockIdx.x * blockDim.x + threadIdx.x;
    int nt = gridDim.x * blockDim.x;
    for (int i = idx0; i < DD * DD; i += nt) {
        int n = i >> 7, k = i & 127;
        float v = W1[k * DD + n];
        __nv_bfloat16 hi = __float2bfloat16(v);
        g_w1t_h[i] = hi;
        g_w1t_l[i] = __float2bfloat16(v - __bfloat162float(hi));
        float v2 = W2[k * DD + n];
        __nv_bfloat16 hi2 = __float2bfloat16(v2);
        g_w2t_h[i] = hi2;
        g_w2t_l[i] = __float2bfloat16(v2 - __bfloat162float(hi2));
    }
    for (int i = idx0; i < HH * DD; i += nt) {
        int n = i >> 7, k = i & 127;
        float v = W3[k * HH + n];
        __nv_bfloat16 hi = __float2bfloat16(v);
        g_w3t_h[i] = hi;
        g_w3t_l[i] = __float2bfloat16(v - __bfloat162float(hi));
    }
    for (int i = idx0; i < DD * HH; i += nt) {
        int n = i >> 9, kk = i & 511;
        float v = W4[kk * DD + n];
        __nv_bfloat16 hi = __float2bfloat16(v);
        g_w4t_h[i] = hi;
        g_w4t_l[i] = __float2bfloat16(v - __bfloat162float(hi));
    }
}

// =================== segmented gathers (no atomics) ===================
// warp per hyperedge: hyper_acc[he] = sum over edges of cn[src]*h[src]
__global__ void k_gather1(const float* __restrict__ h) {
    int w = (blockIdx.x * blockDim.x + threadIdx.x) >> 5;
    if (w >= NH) return;
    int lane = threadIdx.x & 31;
    int beg = g_off_he[w], end = g_off_he[w + 1];
    float4 acc = make_float4(0.f, 0.f, 0.f, 0.f);
    for (int e = beg; e < end; e += 32) {
        int n = end - e;
        if (n > 32) n = 32;
        int idx = g_srt_src[e + (lane < n ? lane : 0)];
        float cnl = rsqrtf(fmaxf((float)g_degi_node[idx], 1.f));
#pragma unroll 4
        for (int j = 0; j < n; j++) {
            int s = __shfl_sync(0xffffffffu, idx, j);
            float c = __shfl_sync(0xffffffffu, cnl, j);
            float4 v = __ldg(&((const float4*)h)[s * 32 + lane]);
            acc.x = fmaf(c, v.x, acc.x);
            acc.y = fmaf(c, v.y, acc.y);
            acc.z = fmaf(c, v.z, acc.z);
            acc.w = fmaf(c, v.w, acc.w);
        }
    }
    ((float4*)g_hyper_acc)[w * 32 + lane] = acc;
}

// warp per node: node_acc[nd] = sum over edges of hyper_msg[dst]
__global__ void k_gather2() {
    int w = (blockIdx.x * blockDim.x + threadIdx.x) >> 5;
    if (w >= NN) return;
    int lane = threadIdx.x & 31;
    int beg = g_off_node[w], end = g_off_node[w + 1];
    float4 acc = make_float4(0.f, 0.f, 0.f, 0.f);
    for (int e = beg; e < end; e += 32) {
        int n = end - e;
        if (n > 32) n = 32;
        int idx = g_srt_dst[e + (lane < n ? lane : 0)];
#pragma unroll 4
        for (int j = 0; j < n; j++) {
            int d = __shfl_sync(0xffffffffu, idx, j);
            float4 v = __ldg(&((const float4*)g_hyper_msg)[d * 32 + lane]);
            acc.x += v.x; acc.y += v.y; acc.z += v.z; acc.w += v.w;
        }
    }
    ((float4*)g_node_acc)[w * 32 + lane] = acc;
}

// =================== HMMA machinery ===================
#define STR 272

__device__ __forceinline__ void mma_bf16(float d[4], uint32_t a0, uint32_t a1,
                                         uint32_t a2, uint32_t a3,
                                         uint32_t b0, uint32_t b1) {
    asm volatile(
        "mma.sync.aligned.m16n8k16.row.col.f32.bf16.bf16.f32 "
        "{%0,%1,%2,%3}, {%4,%5,%6,%7}, {%8,%9}, {%0,%1,%2,%3};"
        : "+f"(d[0]), "+f"(d[1]), "+f"(d[2]), "+f"(d[3])
        : "r"(a0), "r"(a1), "r"(a2), "r"(a3), "r"(b0), "r"(b1));
}

__device__ __forceinline__ void sts_hilo(char* pH, char* pL, float x0, float x1) {
    __nv_bfloat16 h0 = __float2bfloat16(x0), h1 = __float2bfloat16(x1);
    float r0f = x0 - __bfloat162float(h0), r1f = x1 - __bfloat162float(h1);
    *(__nv_bfloat162*)pH = __halves2bfloat162(h0, h1);
    *(__nv_bfloat162*)pL = __halves2bfloat162(__float2bfloat16(r0f), __float2bfloat16(r1f));
}

// D[32 warp-rows x 64 warp-cols] += A[32x128] @ W^T[64x128], 3-term hi/lo.
__device__ __forceinline__ void gemm32x64(const char* smc, int aHoff, int aLoff,
                                          int wHoff, int wLoff,
                                          int R0, int C0, int g, int t,
                                          float d[2][8][4]) {
    const char* pAH = smc + aHoff + (R0 + g) * STR + t * 4;
    const char* pAL = smc + aLoff + (R0 + g) * STR + t * 4;
    const char* pBH = smc + wHoff + (C0 + g) * STR + t * 4;
    const char* pBL = smc + wLoff + (C0 + g) * STR + t * 4;
#pragma unroll 2
    for (int k = 0; k < 8; k++) {
        uint32_t ah[2][4], al[2][4];
#pragma unroll
        for (int i = 0; i < 2; i++) {
            const char* pH = pAH + i * 16 * STR;
            const char* pL = pAL + i * 16 * STR;
            ah[i][0] = *(const uint32_t*)(pH);
            ah[i][1] = *(const uint32_t*)(pH + 8 * STR);
            ah[i][2] = *(const uint32_t*)(pH + 16);
            ah[i][3] = *(const uint32_t*)(pH + 8 * STR + 16);
            al[i][0] = *(const uint32_t*)(pL);
            al[i][1] = *(const uint32_t*)(pL + 8 * STR);
            al[i][2] = *(const uint32_t*)(pL + 16);
            al[i][3] = *(const uint32_t*)(pL + 8 * STR + 16);
        }
#pragma unroll
        for (int j = 0; j < 8; j++) {
            const char* bH = pBH + j * 8 * STR;
            const char* bL = pBL + j * 8 * STR;
            uint32_t bh0 = *(const uint32_t*)(bH);
            uint32_t bh1 = *(const uint32_t*)(bH + 16);
            uint32_t bl0 = *(const uint32_t*)(bL);
            uint32_t bl1 = *(const uint32_t*)(bL + 16);
#pragma unroll
            for (int i = 0; i < 2; i++) {
                mma_bf16(d[i][j], ah[i][0], ah[i][1], ah[i][2], ah[i][3], bh0, bh1);
                mma_bf16(d[i][j], al[i][0], al[i][1], al[i][2], al[i][3], bh0, bh1);
                mma_bf16(d[i][j], ah[i][0], ah[i][1], ah[i][2], ah[i][3], bl0, bl1);
            }
        }
        pAH += 32; pAL += 32; pBH += 32; pBL += 32;
    }
}

__device__ __forceinline__ void stage_w(char* smc, int wHoff, int wLoff,
                                        const __nv_bfloat16* srcH,
                                        const __nv_bfloat16* srcL, int srcStride) {
    int tid = threadIdx.x;
#pragma unroll
    for (int i = tid; i < 2048; i += 256) {
        int r = i >> 4, c8 = (i & 15) * 8;
        uint4 vh = *(const uint4*)(srcH + r * srcStride + c8);
        uint4 vl = *(const uint4*)(srcL + r * srcStride + c8);
        *(uint4*)(smc + wHoff + r * STR + c8 * 2) = vh;
        *(uint4*)(smc + wLoff + r * STR + c8 * 2) = vl;
    }
}

// ---- GEMM1 (hyper): g_hyper_msg = ch^2*(hyper_acc @ W1) + ch*b1 ----
#define SM1_CH 0
#define SM1_B1 512
#define SM1_AH 1024
#define SM1_AL (SM1_AH + 128 * STR)
#define SM1_WH (SM1_AL + 128 * STR)
#define SM1_WL (SM1_WH + 128 * STR)
#define SM1_TOTAL (SM1_WL + 128 * STR)

__global__ __launch_bounds__(256, 1) void k_gemm1_mma(const float* __restrict__ b1f) {
    extern __shared__ char smc[];
    const int tid = threadIdx.x;
    const int warp = tid >> 5, lane = tid & 31;
    const int g = lane >> 2, t = lane & 3;
    const int mg = warp & 3, ng = warp >> 2;
    const int R0 = mg * 32, C0 = ng * 64;
    const int row0 = blockIdx.x * 128;

    if (tid < 128) {
        int r = row0 + tid;
        ((float*)(smc + SM1_CH))[tid] = (r < NH) ? rsqrtf(fmaxf((float)g_degi_he[r], 1.f)) : 0.f;
        ((float*)(smc + SM1_B1))[tid] = b1f[tid];
    }
#pragma unroll
    for (int i = tid; i < 4096; i += 256) {
        int r = i >> 5, c4 = (i & 31) * 4;
        float4 v = make_float4(0.f, 0.f, 0.f, 0.f);
        if (row0 + r < NH) v = *(const float4*)&g_hyper_acc[(row0 + r) * DD + c4];
        char* pH = smc + SM1_AH + r * STR + c4 * 2;
        char* pL = smc + SM1_AL + r * STR + c4 * 2;
        sts_hilo(pH, pL, v.x, v.y);
        sts_hilo(pH + 4, pL + 4, v.z, v.w);
    }
    stage_w(smc, SM1_WH, SM1_WL, g_w1t_h, g_w1t_l, 128);
    __syncthreads();

    float dA[2][8][4];
#pragma unroll
    for (int i = 0; i < 2; i++)
#pragma unroll
        for (int j = 0; j < 8; j++)
#pragma unroll
            for (int p = 0; p < 4; p++) dA[i][j][p] = 0.f;
    gemm32x64(smc, SM1_AH, SM1_AL, SM1_WH, SM1_WL, R0, C0, g, t, dA);

    const float* b1s = (const float*)(smc + SM1_B1);
    const float* chs = (const float*)(smc + SM1_CH);
#pragma unroll
    for (int i = 0; i < 2; i++)
#pragma unroll
        for (int hh = 0; hh < 2; hh++) {
            int row = R0 + i * 16 + hh * 8 + g;
            int gr = row0 + row;
            if (gr >= NH) continue;
            float ch = chs[row];
            float chq = ch * ch;
#pragma unroll
            for (int j = 0; j < 8; j++) {
                int c = C0 + j * 8 + t * 2;
                float2 o;
                o.x = dA[i][j][hh * 2] * chq + b1s[c] * ch;
                o.y = dA[i][j][hh * 2 + 1] * chq + b1s[c + 1] * ch;
                *(float2*)&g_hyper_msg[gr * DD + c] = o;
            }
        }
}

// ---- fused GEMM2 + LN1 + FFN + LN2 ----
#define SM_CN   0
#define SM_B2   512
#define SM_B4   1024
#define SM_G1   1536
#define SM_BE1  2048
#define SM_G2   2560
#define SM_BE2  3072
#define SM_B3   3584
#define SM_SUM  5632
#define SM_SQ   6656
#define SM_A1H  7680
#define SM_A1L  (SM_A1H + 128 * STR)
#define SM_A2H  (SM_A1L + 128 * STR)
#define SM_A2L  (SM_A2H + 128 * STR)
#define SM_WH   (SM_A2L + 128 * STR)
#define SM_WL   (SM_WH + 128 * STR)
#define SM_TOTAL (SM_WL + 128 * STR)

__global__ __launch_bounds__(256, 1) void k_fused_mma(
    const float* __restrict__ h, const float* __restrict__ b2f,
    const float* __restrict__ b3f, const float* __restrict__ b4f,
    const float* __restrict__ g1f, const float* __restrict__ be1f,
    const float* __restrict__ g2f, const float* __restrict__ be2f,
    float* __restrict__ out) {
    extern __shared__ char smc[];
    const int tid = threadIdx.x;
    const int warp = tid >> 5, lane = tid & 31;
    const int g = lane >> 2, t = lane & 3;
    const int mg = warp & 3, ng = warp >> 2;
    const int R0 = mg * 32, C0 = ng * 64;
    const int row0 = blockIdx.x * 128;

    if (tid < 128) {
        int r = row0 + tid;
        ((float*)(smc + SM_CN))[tid]  = (r < NN) ? rsqrtf(fmaxf((float)g_degi_node[r], 1.f)) : 0.f;
        ((float*)(smc + SM_B2))[tid]  = b2f[tid];
        ((float*)(smc + SM_B4))[tid]  = b4f[tid];
        ((float*)(smc + SM_G1))[tid]  = g1f[tid];
        ((float*)(smc + SM_BE1))[tid] = be1f[tid];
        ((float*)(smc + SM_G2))[tid]  = g2f[tid];
        ((float*)(smc + SM_BE2))[tid] = be2f[tid];
    }
    for (int i = tid; i < 512; i += 256) ((float*)(smc + SM_B3))[i] = b3f[i];

#pragma unroll
    for (int i = tid; i < 4096; i += 256) {
        int r = i >> 5, c4 = (i & 31) * 4;
        float4 v = make_float4(0.f, 0.f, 0.f, 0.f);
        if (row0 + r < NN) v = *(const float4*)&g_node_acc[(row0 + r) * DD + c4];
        char* pH = smc + SM_A1H + r * STR + c4 * 2;
        char* pL = smc + SM_A1L + r * STR + c4 * 2;
        sts_hilo(pH, pL, v.x, v.y);
        sts_hilo(pH + 4, pL + 4, v.z, v.w);
    }
    stage_w(smc, SM_WH, SM_WL, g_w2t_h, g_w2t_l, 128);
    __syncthreads();

    const float* cns = (const float*)(smc + SM_CN);
    float* sums = (float*)(smc + SM_SUM);   // [2][128]
    float* sqs  = (float*)(smc + SM_SQ);

    // ---- GEMM2 ----
    float dA[2][8][4];
#pragma unroll
    for (int i = 0; i < 2; i++)
#pragma unroll
        for (int j = 0; j < 8; j++)
#pragma unroll
            for (int p = 0; p < 4; p++) dA[i][j][p] = 0.f;
    gemm32x64(smc, SM_A1H, SM_A1L, SM_WH, SM_WL, R0, C0, g, t, dA);

    // ---- epilogue: h1 = LN1(h + cn*D + b2) -> A1 planes ----
    {
        const float* b2s = (const float*)(smc + SM_B2);
        float rs[2][2], rq[2][2];
#pragma unroll
        for (int i = 0; i < 2; i++)
#pragma unroll
            for (int hh = 0; hh < 2; hh++) {
                int row = R0 + i * 16 + hh * 8 + g;
                int grow = row0 + row;
                float cn = cns[row];
                float s = 0.f, q = 0.f;
#pragma unroll
                for (int j = 0; j < 8; j++) {
                    int c = C0 + j * 8 + t * 2;
                    float2 hv = make_float2(0.f, 0.f);
                    if (grow < NN) hv = *(const float2*)&h[grow * DD + c];
                    float x0 = hv.x + cn * dA[i][j][hh * 2] + b2s[c];
                    float x1 = hv.y + cn * dA[i][j][hh * 2 + 1] + b2s[c + 1];
                    dA[i][j][hh * 2] = x0;
                    dA[i][j][hh * 2 + 1] = x1;
                    s += x0 + x1;
                    q += x0 * x0 + x1 * x1;
                }
                rs[i][hh] = s; rq[i][hh] = q;
            }
#pragma unroll
        for (int i = 0; i < 2; i++)
#pragma unroll
            for (int hh = 0; hh < 2; hh++) {
                rs[i][hh] += __shfl_xor_sync(~0u, rs[i][hh], 1);
                rs[i][hh] += __shfl_xor_sync(~0u, rs[i][hh], 2);
                rq[i][hh] += __shfl_xor_sync(~0u, rq[i][hh], 1);
                rq[i][hh] += __shfl_xor_sync(~0u, rq[i][hh], 2);
            }
        if (t == 0) {
#pragma unroll
            for (int i = 0; i < 2; i++)
#pragma unroll
                for (int hh = 0; hh < 2; hh++) {
                    int row = R0 + i * 16 + hh * 8 + g;
                    sums[ng * 128 + row] = rs[i][hh];
                    sqs[ng * 128 + row] = rq[i][hh];
                }
        }
        __syncthreads();
        const float* g1s = (const float*)(smc + SM_G1);
        const float* be1s = (const float*)(smc + SM_BE1);
#pragma unroll
        for (int i = 0; i < 2; i++)
#pragma unroll
            for (int hh = 0; hh < 2; hh++) {
                int row = R0 + i * 16 + hh * 8 + g;
                float ts = sums[row] + sums[128 + row];
                float tq = sqs[row] + sqs[128 + row];
                float mu = ts * (1.f / 128.f);
                float inv = rsqrtf(fmaxf(tq * (1.f / 128.f) - mu * mu, 0.f) + 1e-5f);
#pragma unroll
                for (int j = 0; j < 8; j++) {
                    int c = C0 + j * 8 + t * 2;
                    float y0 = (dA[i][j][hh * 2] - mu) * inv * g1s[c] + be1s[c];
                    float y1 = (dA[i][j][hh * 2 + 1] - mu) * inv * g1s[c + 1] + be1s[c + 1];
                    sts_hilo(smc + SM_A1H + row * STR + c * 2,
                             smc + SM_A1L + row * STR + c * 2, y0, y1);
                }
            }
    }

    // ---- FFN ----
    float dC[2][8][4];
#pragma unroll
    for (int i = 0; i < 2; i++)
#pragma unroll
        for (int j = 0; j < 8; j++)
#pragma unroll
            for (int p = 0; p < 4; p++) dC[i][j][p] = 0.f;

    for (int nc = 0; nc < 4; nc++) {
        __syncthreads();
        stage_w(smc, SM_WH, SM_WL, g_w3t_h + nc * 128 * DD, g_w3t_l + nc * 128 * DD, 128);
        __syncthreads();
        float dB[2][8][4];
#pragma unroll
        for (int i = 0; i < 2; i++)
#pragma unroll
            for (int j = 0; j < 8; j++)
#pragma unroll
                for (int p = 0; p < 4; p++) dB[i][j][p] = 0.f;
        gemm32x64(smc, SM_A1H, SM_A1L, SM_WH, SM_WL, R0, C0, g, t, dB);
        const float* b3s = (const float*)(smc + SM_B3) + nc * 128;
#pragma unroll
        for (int i = 0; i < 2; i++)
#pragma unroll
            for (int hh = 0; hh < 2; hh++) {
                int row = R0 + i * 16 + hh * 8 + g;
#pragma unroll
                for (int j = 0; j < 8; j++) {
                    int c = C0 + j * 8 + t * 2;
                    float x0 = fmaxf(dB[i][j][hh * 2] + b3s[c], 0.f);
                    float x1 = fmaxf(dB[i][j][hh * 2 + 1] + b3s[c + 1], 0.f);
                    sts_hilo(smc + SM_A2H + row * STR + c * 2,
                             smc + SM_A2L + row * STR + c * 2, x0, x1);
                }
            }
        __syncthreads();
        stage_w(smc, SM_WH, SM_WL, g_w4t_h + nc * 128, g_w4t_l + nc * 128, 512);
        __syncthreads();
        gemm32x64(smc, SM_A2H, SM_A2L, SM_WH, SM_WL, R0, C0, g, t, dC);
    }

    // ---- final epilogue: LN2(D2 + b4 + h1) -> out ----
    {
        const float* b4s = (const float*)(smc + SM_B4);
        float rs[2][2], rq[2][2];
#pragma unroll
        for (int i = 0; i < 2; i++)
#pragma unroll
            for (int hh = 0; hh < 2; hh++) {
                int row = R0 + i * 16 + hh * 8 + g;
                float s = 0.f, q = 0.f;
#pragma unroll
                for (int j = 0; j < 8; j++) {
                    int c = C0 + j * 8 + t * 2;
                    const char* pH = smc + SM_A1H + row * STR + c * 2;
                    const char* pL = smc + SM_A1L + row * STR + c * 2;
                    __nv_bfloat162 hh2 = *(const __nv_bfloat162*)(pH);
                    __nv_bfloat162 ll2 = *(const __nv_bfloat162*)(pL);
                    float x0 = dC[i][j][hh * 2] + b4s[c]
                             + __bfloat162float(hh2.x) + __bfloat162float(ll2.x);
                    float x1 = dC[i][j][hh * 2 + 1] + b4s[c + 1]
                             + __bfloat162float(hh2.y) + __bfloat162float(ll2.y);
                    dC[i][j][hh * 2] = x0;
                    dC[i][j][hh * 2 + 1] = x1;
                    s += x0 + x1;
                    q += x0 * x0 + x1 * x1;
                }
                rs[i][hh] = s; rq[i][hh] = q;
            }
#pragma unroll
        for (int i = 0; i < 2; i++)
#pragma unroll
            for (int hh = 0; hh < 2; hh++) {
                rs[i][hh] += __shfl_xor_sync(~0u, rs[i][hh], 1);
                rs[i][hh] += __shfl_xor_sync(~0u, rs[i][hh], 2);
                rq[i][hh] += __shfl_xor_sync(~0u, rq[i][hh], 1);
                rq[i][hh] += __shfl_xor_sync(~0u, rq[i][hh], 2);
            }
        if (t == 0) {
#pragma unroll
            for (int i = 0; i < 2; i++)
#pragma unroll
                for (int hh = 0; hh < 2; hh++) {
                    int row = R0 + i * 16 + hh * 8 + g;
                    sums[ng * 128 + row] = rs[i][hh];
                    sqs[ng * 128 + row] = rq[i][hh];
                }
        }
        __syncthreads();
        const float* g2s = (const float*)(smc + SM_G2);
        const float* be2s = (const float*)(smc + SM_BE2);
#pragma unroll
        for (int i = 0; i < 2; i++)
#pragma unroll
            for (int hh = 0; hh < 2; hh++) {
                int row = R0 + i * 16 + hh * 8 + g;
                int grow = row0 + row;
                float ts = sums[row] + sums[128 + row];
                float tq = sqs[row] + sqs[128 + row];
                float mu = ts * (1.f / 128.f);
                float inv = rsqrtf(fmaxf(tq * (1.f / 128.f) - mu * mu, 0.f) + 1e-5f);
                if (grow < NN) {
#pragma unroll
                    for (int j = 0; j < 8; j++) {
                        int c = C0 + j * 8 + t * 2;
                        float2 o;
                        o.x = (dC[i][j][hh * 2] - mu) * inv * g2s[c] + be2s[c];
                        o.y = (dC[i][j][hh * 2 + 1] - mu) * inv * g2s[c + 1] + be2s[c + 1];
                        *(float2*)&out[grow * DD + c] = o;
                    }
                }
            }
    }
}

// ---------------- launch ----------------
extern "C" void kernel_launch(void* const* d_in, const int* in_sizes, int n_in,
                              void* d_out, int out_size) {
    const float* h   = (const float*)d_in[0];
    const int*   src = (const int*)d_in[1];
    const int*   dst = (const int*)d_in[2];
    const float* W1  = (const float*)d_in[3];
    const float* b1  = (const float*)d_in[4];
    const float* W2  = (const float*)d_in[5];
    const float* b2  = (const float*)d_in[6];
    const float* W3  = (const float*)d_in[7];
    const float* b3  = (const float*)d_in[8];
    const float* W4  = (const float*)d_in[9];
    const float* b4  = (const float*)d_in[10];
    const float* g1  = (const float*)d_in[11];
    const float* be1 = (const float*)d_in[12];
    const float* g2  = (const float*)d_in[13];
    const float* be2 = (const float*)d_in[14];
    float* out = (float*)d_out;

    cudaFuncSetAttribute(k_gemm1_mma, cudaFuncAttributeMaxDynamicSharedMemorySize, SM1_TOTAL);
    cudaFuncSetAttribute(k_fused_mma, cudaFuncAttributeMaxDynamicSharedMemorySize, SM_TOTAL);

    k_zero<<<512, 256>>>();
    k_wconv<<<288, 256>>>(W1, W2, W3, W4);
    k_deg<<<(NE + 255) / 256, 256>>>(src, dst);
    k_scan_p1<<<NB_HE + NB_NODE, 1024>>>();
    k_scan_p2<<<1, 32>>>();
    k_scan_p3<<<NB_HE + NB_NODE, 1024>>>();
    k_place<<<(NE + 255) / 256, 256>>>(src, dst);
    k_gather1<<<(NH * 32 + 255) / 256, 256>>>(h);
    k_gemm1_mma<<<(NH + 127) / 128, 256, SM1_TOTAL>>>(b1);
    k_gather2<<<(NN * 32 + 255) / 256, 256>>>();
    k_fused_mma<<<(NN + 127) / 128, 256, SM_TOTAL>>>(h, b2, b3, b4,
                                                     g1, be1, g2, be2, out);
}

// round 10
// speedup vs baseline: 2.3143x; 1.0467x over previous
#include <cuda_runtime.h>
#include <cuda_bf16.h>
#include <cstdint>

#define NN 100000
#define NH 20000
#define NE 1600000
#define DD 128
#define HH 512

#define NB_HE 20      // ceil(NH/1024)
#define NB_NODE 98    // ceil(NN/1024)

// ---------------- scratch (device globals; no allocation allowed) ----------------
__device__ __align__(16) int g_degi_node[NN];
__device__ __align__(16) int g_degi_he[NH];
__device__ __align__(16) int g_off_node[NN];   // after k_place: off[w] = orig off[w+1]
__device__ __align__(16) int g_off_he[NH];
__device__ __align__(16) int g_bsum[NB_HE + NB_NODE];
__device__ __align__(16) int g_srt_src[NE];     // edges sorted by dst -> src ids
__device__ __align__(16) int g_srt_dst[NE];     // edges sorted by src -> dst ids
__device__ __align__(16) float g_hyper_acc[NH * DD];
__device__ __align__(16) float g_hyper_msg[NH * DD];
__device__ __align__(16) float g_node_acc[NN * DD];
// pre-transposed bf16 hi/lo weight planes: [n][k] layout
__device__ __align__(16) __nv_bfloat16 g_w1t_h[DD * DD];
__device__ __align__(16) __nv_bfloat16 g_w1t_l[DD * DD];
__device__ __align__(16) __nv_bfloat16 g_w2t_h[DD * DD];
__device__ __align__(16) __nv_bfloat16 g_w2t_l[DD * DD];
__device__ __align__(16) __nv_bfloat16 g_w3t_h[HH * DD];   // [n=0..511][k=0..127]
__device__ __align__(16) __nv_bfloat16 g_w3t_l[HH * DD];
__device__ __align__(16) __nv_bfloat16 g_w4t_h[DD * HH];   // [n=0..127][kk=0..511]
__device__ __align__(16) __nv_bfloat16 g_w4t_l[DD * HH];

// =================== preprocessing kernels ===================
__global__ void k_zero() {
    int idx = blockIdx.x * blockDim.x + threadIdx.x;
    int nthr = gridDim.x * blockDim.x;
    for (int i = idx; i < NN; i += nthr) g_degi_node[i] = 0;
    for (int i = idx; i < NH; i += nthr) g_degi_he[i] = 0;
}

__global__ void k_deg(const int* __restrict__ src, const int* __restrict__ dst) {
    int e = blockIdx.x * blockDim.x + threadIdx.x;
    if (e < NE) {
        atomicAdd(&g_degi_node[src[e]], 1);
        atomicAdd(&g_degi_he[dst[e]], 1);
    }
}

// ---- 2-pass multi-block exclusive scan (blocks 0..NB_HE-1: he, rest: node) ----
__global__ void k_scan_p1() {
    int b = blockIdx.x;
    const int* __restrict__ cnt;
    int* __restrict__ off;
    int n, lb;
    if (b < NB_HE) { cnt = g_degi_he; off = g_off_he; n = NH; lb = b; }
    else           { cnt = g_degi_node; off = g_off_node; n = NN; lb = b - NB_HE; }
    __shared__ int sh[1024];
    int tid = threadIdx.x;
    int i = lb * 1024 + tid;
    int v = (i < n) ? cnt[i] : 0;
    sh[tid] = v;
    __syncthreads();
    for (int o = 1; o < 1024; o <<= 1) {
        int t = (tid >= o) ? sh[tid - o] : 0;
        __syncthreads();
        sh[tid] += t;
        __syncthreads();
    }
    if (i < n) off[i] = sh[tid] - v;
    if (tid == 1023) g_bsum[b] = sh[1023];
}

// each block redundantly prefix-sums its matrix's block totals (<=98 adds, MLP-friendly)
__global__ void k_scan_p2p3() {
    __shared__ int base;
    int b = blockIdx.x;
    int* __restrict__ off;
    int n, lb, lo;
    if (b < NB_HE) { off = g_off_he; n = NH; lb = b; lo = 0; }
    else           { off = g_off_node; n = NN; lb = b - NB_HE; lo = NB_HE; }
    if (threadIdx.x == 0) {
        int run = 0;
#pragma unroll 4
        for (int i = lo; i < b; i++) run += g_bsum[i];
        base = run;
    }
    __syncthreads();
    int add = base;
    int i = lb * 1024 + threadIdx.x;
    if (i < n) off[i] += add;
}

// atomicAdd directly on off: returned value is the slot; off[w] ends at orig off[w+1]
__global__ void k_place(const int* __restrict__ src, const int* __restrict__ dst) {
    int e = blockIdx.x * blockDim.x + threadIdx.x;
    if (e < NE) {
        int s = src[e], d = dst[e];
        int p1 = atomicAdd(&g_off_he[d], 1);
        g_srt_src[p1] = s;
        int p2 = atomicAdd(&g_off_node[s], 1);
        g_srt_dst[p2] = d;
    }
}

// tiled weight transpose + bf16 hi/lo precompute (coalesced both sides)
__global__ void k_wconv_t(const float* __restrict__ W1, const float* __restrict__ W2,
                          const float* __restrict__ W3, const float* __restrict__ W4) {
    __shared__ float tile[32][33];
    int b = blockIdx.x;
    const float* srcm;
    __nv_bfloat16 *dH, *dL;
    int kdim, ndim, local;
    if (b < 16)       { srcm = W1; dH = g_w1t_h; dL = g_w1t_l; kdim = 128; ndim = 128; local = b; }
    else if (b < 32)  { srcm = W2; dH = g_w2t_h; dL = g_w2t_l; kdim = 128; ndim = 128; local = b - 16; }
    else if (b < 96)  { srcm = W3; dH = g_w3t_h; dL = g_w3t_l; kdim = 128; ndim = 512; local = b - 32; }
    else              { srcm = W4; dH = g_w4t_h; dL = g_w4t_l; kdim = 512; ndim = 128; local = b - 96; }
    int ktiles = kdim >> 5;
    int kt = local % ktiles, nt = local / ktiles;
    int tx = threadIdx.x & 31, ty = threadIdx.x >> 5;
#pragma unroll
    for (int p = 0; p < 4; p++) {
        int r = p * 8 + ty;
        tile[r][tx] = srcm[(kt * 32 + r) * ndim + nt * 32 + tx];
    }
    __syncthreads();
#pragma unroll
    for (int p = 0; p < 4; p++) {
        int rr = p * 8 + ty;             // n-direction
        float v = tile[tx][rr];          // k = kt*32+tx
        __nv_bfloat16 hi = __float2bfloat16(v);
        int o = (nt * 32 + rr) * kdim + kt * 32 + tx;
        dH[o] = hi;
        dL[o] = __float2bfloat16(v - __bfloat162float(hi));
    }
}

// =================== segmented gathers (no atomics) ===================
__global__ void k_gather1(const float* __restrict__ h) {
    int w = (blockIdx.x * blockDim.x + threadIdx.x) >> 5;
    if (w >= NH) return;
    int lane = threadIdx.x & 31;
    int beg = w ? g_off_he[w - 1] : 0, end = g_off_he[w];
    float4 acc = make_float4(0.f, 0.f, 0.f, 0.f);
    for (int e = beg; e < end; e += 32) {
        int n = end - e;
        if (n > 32) n = 32;
        int idx = g_srt_src[e + (lane < n ? lane : 0)];
        float cnl = rsqrtf(fmaxf((float)g_degi_node[idx], 1.f));
#pragma unroll 4
        for (int j = 0; j < n; j++) {
            int s = __shfl_sync(0xffffffffu, idx, j);
            float c = __shfl_sync(0xffffffffu, cnl, j);
            float4 v = __ldg(&((const float4*)h)[s * 32 + lane]);
            acc.x = fmaf(c, v.x, acc.x);
            acc.y = fmaf(c, v.y, acc.y);
            acc.z = fmaf(c, v.z, acc.z);
            acc.w = fmaf(c, v.w, acc.w);
        }
    }
    ((float4*)g_hyper_acc)[w * 32 + lane] = acc;
}

__global__ void k_gather2() {
    int w = (blockIdx.x * blockDim.x + threadIdx.x) >> 5;
    if (w >= NN) return;
    int lane = threadIdx.x & 31;
    int beg = w ? g_off_node[w - 1] : 0, end = g_off_node[w];
    float4 acc = make_float4(0.f, 0.f, 0.f, 0.f);
    for (int e = beg; e < end; e += 32) {
        int n = end - e;
        if (n > 32) n = 32;
        int idx = g_srt_dst[e + (lane < n ? lane : 0)];
#pragma unroll 4
        for (int j = 0; j < n; j++) {
            int d = __shfl_sync(0xffffffffu, idx, j);
            float4 v = __ldg(&((const float4*)g_hyper_msg)[d * 32 + lane]);
            acc.x += v.x; acc.y += v.y; acc.z += v.z; acc.w += v.w;
        }
    }
    ((float4*)g_node_acc)[w * 32 + lane] = acc;
}

// =================== HMMA machinery ===================
#define STR 272

__device__ __forceinline__ void mma_bf16(float d[4], uint32_t a0, uint32_t a1,
                                         uint32_t a2, uint32_t a3,
                                         uint32_t b0, uint32_t b1) {
    asm volatile(
        "mma.sync.aligned.m16n8k16.row.col.f32.bf16.bf16.f32 "
        "{%0,%1,%2,%3}, {%4,%5,%6,%7}, {%8,%9}, {%0,%1,%2,%3};"
        : "+f"(d[0]), "+f"(d[1]), "+f"(d[2]), "+f"(d[3])
        : "r"(a0), "r"(a1), "r"(a2), "r"(a3), "r"(b0), "r"(b1));
}

__device__ __forceinline__ void sts_hilo(char* pH, char* pL, float x0, float x1) {
    __nv_bfloat16 h0 = __float2bfloat16(x0), h1 = __float2bfloat16(x1);
    float r0f = x0 - __bfloat162float(h0), r1f = x1 - __bfloat162float(h1);
    *(__nv_bfloat162*)pH = __halves2bfloat162(h0, h1);
    *(__nv_bfloat162*)pL = __halves2bfloat162(__float2bfloat16(r0f), __float2bfloat16(r1f));
}

// D[32 warp-rows x 64 warp-cols] += A[32x128] @ W^T[64x128], 3-term hi/lo.
__device__ __forceinline__ void gemm32x64(const char* smc, int aHoff, int aLoff,
                                          int wHoff, int wLoff,
                                          int R0, int C0, int g, int t,
                                          float d[2][8][4]) {
    const char* pAH = smc + aHoff + (R0 + g) * STR + t * 4;
    const char* pAL = smc + aLoff + (R0 + g) * STR + t * 4;
    const char* pBH = smc + wHoff + (C0 + g) * STR + t * 4;
    const char* pBL = smc + wLoff + (C0 + g) * STR + t * 4;
#pragma unroll 2
    for (int k = 0; k < 8; k++) {
        uint32_t ah[2][4], al[2][4];
#pragma unroll
        for (int i = 0; i < 2; i++) {
            const char* pH = pAH + i * 16 * STR;
            const char* pL = pAL + i * 16 * STR;
            ah[i][0] = *(const uint32_t*)(pH);
            ah[i][1] = *(const uint32_t*)(pH + 8 * STR);
            ah[i][2] = *(const uint32_t*)(pH + 16);
            ah[i][3] = *(const uint32_t*)(pH + 8 * STR + 16);
            al[i][0] = *(const uint32_t*)(pL);
            al[i][1] = *(const uint32_t*)(pL + 8 * STR);
            al[i][2] = *(const uint32_t*)(pL + 16);
            al[i][3] = *(const uint32_t*)(pL + 8 * STR + 16);
        }
#pragma unroll
        for (int j = 0; j < 8; j++) {
            const char* bH = pBH + j * 8 * STR;
            const char* bL = pBL + j * 8 * STR;
            uint32_t bh0 = *(const uint32_t*)(bH);
            uint32_t bh1 = *(const uint32_t*)(bH + 16);
            uint32_t bl0 = *(const uint32_t*)(bL);
            uint32_t bl1 = *(const uint32_t*)(bL + 16);
#pragma unroll
            for (int i = 0; i < 2; i++) {
                mma_bf16(d[i][j], ah[i][0], ah[i][1], ah[i][2], ah[i][3], bh0, bh1);
                mma_bf16(d[i][j], al[i][0], al[i][1], al[i][2], al[i][3], bh0, bh1);
                mma_bf16(d[i][j], ah[i][0], ah[i][1], ah[i][2], ah[i][3], bl0, bl1);
            }
        }
        pAH += 32; pAL += 32; pBH += 32; pBL += 32;
    }
}

// async W staging: issue LDGSTS then overlap other work; wait with W_WAIT before use
__device__ __forceinline__ void stage_w_async(char* smc, int wHoff, int wLoff,
                                              const __nv_bfloat16* srcH,
                                              const __nv_bfloat16* srcL, int srcStride) {
    int tid = threadIdx.x;
    unsigned dH = (unsigned)__cvta_generic_to_shared(smc + wHoff);
    unsigned dL = (unsigned)__cvta_generic_to_shared(smc + wLoff);
#pragma unroll
    for (int i = tid; i < 2048; i += 256) {
        int r = i >> 4, c8 = (i & 15) * 8;
        asm volatile("cp.async.cg.shared.global [%0], [%1], 16;"
                     :: "r"(dH + r * STR + c8 * 2), "l"(srcH + r * srcStride + c8) : "memory");
        asm volatile("cp.async.cg.shared.global [%0], [%1], 16;"
                     :: "r"(dL + r * STR + c8 * 2), "l"(srcL + r * srcStride + c8) : "memory");
    }
    asm volatile("cp.async.commit_group;" ::: "memory");
}
#define W_WAIT() asm volatile("cp.async.wait_group 0;" ::: "memory")

// ---- GEMM1 (hyper): g_hyper_msg = ch^2*(hyper_acc @ W1) + ch*b1 ----
#define SM1_CH 0
#define SM1_B1 512
#define SM1_AH 1024
#define SM1_AL (SM1_AH + 128 * STR)
#define SM1_WH (SM1_AL + 128 * STR)
#define SM1_WL (SM1_WH + 128 * STR)
#define SM1_TOTAL (SM1_WL + 128 * STR)

__global__ __launch_bounds__(256, 1) void k_gemm1_mma(const float* __restrict__ b1f) {
    extern __shared__ char smc[];
    const int tid = threadIdx.x;
    const int warp = tid >> 5, lane = tid & 31;
    const int g = lane >> 2, t = lane & 3;
    const int mg = warp & 3, ng = warp >> 2;
    const int R0 = mg * 32, C0 = ng * 64;
    const int row0 = blockIdx.x * 128;

    stage_w_async(smc, SM1_WH, SM1_WL, g_w1t_h, g_w1t_l, 128);

    if (tid < 128) {
        int r = row0 + tid;
        ((float*)(smc + SM1_CH))[tid] = (r < NH) ? rsqrtf(fmaxf((float)g_degi_he[r], 1.f)) : 0.f;
        ((float*)(smc + SM1_B1))[tid] = b1f[tid];
    }
#pragma unroll
    for (int i = tid; i < 4096; i += 256) {
        int r = i >> 5, c4 = (i & 31) * 4;
        float4 v = make_float4(0.f, 0.f, 0.f, 0.f);
        if (row0 + r < NH) v = *(const float4*)&g_hyper_acc[(row0 + r) * DD + c4];
        char* pH = smc + SM1_AH + r * STR + c4 * 2;
        char* pL = smc + SM1_AL + r * STR + c4 * 2;
        sts_hilo(pH, pL, v.x, v.y);
        sts_hilo(pH + 4, pL + 4, v.z, v.w);
    }
    W_WAIT();
    __syncthreads();

    float dA[2][8][4];
#pragma unroll
    for (int i = 0; i < 2; i++)
#pragma unroll
        for (int j = 0; j < 8; j++)
#pragma unroll
            for (int p = 0; p < 4; p++) dA[i][j][p] = 0.f;
    gemm32x64(smc, SM1_AH, SM1_AL, SM1_WH, SM1_WL, R0, C0, g, t, dA);

    const float* b1s = (const float*)(smc + SM1_B1);
    const float* chs = (const float*)(smc + SM1_CH);
#pragma unroll
    for (int i = 0; i < 2; i++)
#pragma unroll
        for (int hh = 0; hh < 2; hh++) {
            int row = R0 + i * 16 + hh * 8 + g;
            int gr = row0 + row;
            if (gr >= NH) continue;
            float ch = chs[row];
            float chq = ch * ch;
#pragma unroll
            for (int j = 0; j < 8; j++) {
                int c = C0 + j * 8 + t * 2;
                float2 o;
                o.x = dA[i][j][hh * 2] * chq + b1s[c] * ch;
                o.y = dA[i][j][hh * 2 + 1] * chq + b1s[c + 1] * ch;
                *(float2*)&g_hyper_msg[gr * DD + c] = o;
            }
        }
}

// ---- fused GEMM2 + LN1 + FFN + LN2 ----
#define SM_CN   0
#define SM_B2   512
#define SM_B4   1024
#define SM_G1   1536
#define SM_BE1  2048
#define SM_G2   2560
#define SM_BE2  3072
#define SM_B3   3584
#define SM_SUM  5632
#define SM_SQ   6656
#define SM_A1H  7680
#define SM_A1L  (SM_A1H + 128 * STR)
#define SM_A2H  (SM_A1L + 128 * STR)
#define SM_A2L  (SM_A2H + 128 * STR)
#define SM_WH   (SM_A2L + 128 * STR)
#define SM_WL   (SM_WH + 128 * STR)
#define SM_TOTAL (SM_WL + 128 * STR)

__global__ __launch_bounds__(256, 1) void k_fused_mma(
    const float* __restrict__ h, const float* __restrict__ b2f,
    const float* __restrict__ b3f, const float* __restrict__ b4f,
    const float* __restrict__ g1f, const float* __restrict__ be1f,
    const float* __restrict__ g2f, const float* __restrict__ be2f,
    float* __restrict__ out) {
    extern __shared__ char smc[];
    const int tid = threadIdx.x;
    const int warp = tid >> 5, lane = tid & 31;
    const int g = lane >> 2, t = lane & 3;
    const int mg = warp & 3, ng = warp >> 2;
    const int R0 = mg * 32, C0 = ng * 64;
    const int row0 = blockIdx.x * 128;

    stage_w_async(smc, SM_WH, SM_WL, g_w2t_h, g_w2t_l, 128);

    if (tid < 128) {
        int r = row0 + tid;
        ((float*)(smc + SM_CN))[tid]  = (r < NN) ? rsqrtf(fmaxf((float)g_degi_node[r], 1.f)) : 0.f;
        ((float*)(smc + SM_B2))[tid]  = b2f[tid];
        ((float*)(smc + SM_B4))[tid]  = b4f[tid];
        ((float*)(smc + SM_G1))[tid]  = g1f[tid];
        ((float*)(smc + SM_BE1))[tid] = be1f[tid];
        ((float*)(smc + SM_G2))[tid]  = g2f[tid];
        ((float*)(smc + SM_BE2))[tid] = be2f[tid];
    }
    for (int i = tid; i < 512; i += 256) ((float*)(smc + SM_B3))[i] = b3f[i];

#pragma unroll
    for (int i = tid; i < 4096; i += 256) {
        int r = i >> 5, c4 = (i & 31) * 4;
        float4 v = make_float4(0.f, 0.f, 0.f, 0.f);
        if (row0 + r < NN) v = *(const float4*)&g_node_acc[(row0 + r) * DD + c4];
        char* pH = smc + SM_A1H + r * STR + c4 * 2;
        char* pL = smc + SM_A1L + r * STR + c4 * 2;
        sts_hilo(pH, pL, v.x, v.y);
        sts_hilo(pH + 4, pL + 4, v.z, v.w);
    }
    W_WAIT();
    __syncthreads();

    const float* cns = (const float*)(smc + SM_CN);
    float* sums = (float*)(smc + SM_SUM);   // [2][128]
    float* sqs  = (float*)(smc + SM_SQ);

    // ---- GEMM2 ----
    float dA[2][8][4];
#pragma unroll
    for (int i = 0; i < 2; i++)
#pragma unroll
        for (int j = 0; j < 8; j++)
#pragma unroll
            for (int p = 0; p < 4; p++) dA[i][j][p] = 0.f;
    gemm32x64(smc, SM_A1H, SM_A1L, SM_WH, SM_WL, R0, C0, g, t, dA);
    __syncthreads();                       // all warps done reading W2
    stage_w_async(smc, SM_WH, SM_WL, g_w3t_h, g_w3t_l, 128);   // W3 chunk 0, overlaps LN1

    // ---- epilogue: h1 = LN1(h + cn*D + b2) -> A1 planes ----
    {
        const float* b2s = (const float*)(smc + SM_B2);
        float rs[2][2], rq[2][2];
#pragma unroll
        for (int i = 0; i < 2; i++)
#pragma unroll
            for (int hh = 0; hh < 2; hh++) {
                int row = R0 + i * 16 + hh * 8 + g;
                int grow = row0 + row;
                float cn = cns[row];
                float s = 0.f, q = 0.f;
#pragma unroll
                for (int j = 0; j < 8; j++) {
                    int c = C0 + j * 8 + t * 2;
                    float2 hv = make_float2(0.f, 0.f);
                    if (grow < NN) hv = *(const float2*)&h[grow * DD + c];
                    float x0 = hv.x + cn * dA[i][j][hh * 2] + b2s[c];
                    float x1 = hv.y + cn * dA[i][j][hh * 2 + 1] + b2s[c + 1];
                    dA[i][j][hh * 2] = x0;
                    dA[i][j][hh * 2 + 1] = x1;
                    s += x0 + x1;
                    q += x0 * x0 + x1 * x1;
                }
                rs[i][hh] = s; rq[i][hh] = q;
            }
#pragma unroll
        for (int i = 0; i < 2; i++)
#pragma unroll
            for (int hh = 0; hh < 2; hh++) {
                rs[i][hh] += __shfl_xor_sync(~0u, rs[i][hh], 1);
                rs[i][hh] += __shfl_xor_sync(~0u, rs[i][hh], 2);
                rq[i][hh] += __shfl_xor_sync(~0u, rq[i][hh], 1);
                rq[i][hh] += __shfl_xor_sync(~0u, rq[i][hh], 2);
            }
        if (t == 0) {
#pragma unroll
            for (int i = 0; i < 2; i++)
#pragma unroll
                for (int hh = 0; hh < 2; hh++) {
                    int row = R0 + i * 16 + hh * 8 + g;
                    sums[ng * 128 + row] = rs[i][hh];
                    sqs[ng * 128 + row] = rq[i][hh];
                }
        }
        __syncthreads();
        const float* g1s = (const float*)(smc + SM_G1);
        const float* be1s = (const float*)(smc + SM_BE1);
#pragma unroll
        for (int i = 0; i < 2; i++)
#pragma unroll
            for (int hh = 0; hh < 2; hh++) {
                int row = R0 + i * 16 + hh * 8 + g;
                float ts = sums[row] + sums[128 + row];
                float tq = sqs[row] + sqs[128 + row];
                float mu = ts * (1.f / 128.f);
                float inv = rsqrtf(fmaxf(tq * (1.f / 128.f) - mu * mu, 0.f) + 1e-5f);
#pragma unroll
                for (int j = 0; j < 8; j++) {
                    int c = C0 + j * 8 + t * 2;
                    float y0 = (dA[i][j][hh * 2] - mu) * inv * g1s[c] + be1s[c];
                    float y1 = (dA[i][j][hh * 2 + 1] - mu) * inv * g1s[c + 1] + be1s[c + 1];
                    sts_hilo(smc + SM_A1H + row * STR + c * 2,
                             smc + SM_A1L + row * STR + c * 2, y0, y1);
                }
            }
    }
    W_WAIT();
    __syncthreads();    // W3 chunk 0 ready + A1(h1) visible

    // ---- FFN ----
    float dC[2][8][4];
#pragma unroll
    for (int i = 0; i < 2; i++)
#pragma unroll
        for (int j = 0; j < 8; j++)
#pragma unroll
            for (int p = 0; p < 4; p++) dC[i][j][p] = 0.f;

    for (int nc = 0; nc < 4; nc++) {
        float dB[2][8][4];
#pragma unroll
        for (int i = 0; i < 2; i++)
#pragma unroll
            for (int j = 0; j < 8; j++)
#pragma unroll
                for (int p = 0; p < 4; p++) dB[i][j][p] = 0.f;
        gemm32x64(smc, SM_A1H, SM_A1L, SM_WH, SM_WL, R0, C0, g, t, dB);
        __syncthreads();                   // W3 chunk free
        stage_w_async(smc, SM_WH, SM_WL, g_w4t_h + nc * 128, g_w4t_l + nc * 128, 512);
        const float* b3s = (const float*)(smc + SM_B3) + nc * 128;
#pragma unroll
        for (int i = 0; i < 2; i++)
#pragma unroll
            for (int hh = 0; hh < 2; hh++) {
                int row = R0 + i * 16 + hh * 8 + g;
#pragma unroll
                for (int j = 0; j < 8; j++) {
                    int c = C0 + j * 8 + t * 2;
                    float x0 = fmaxf(dB[i][j][hh * 2] + b3s[c], 0.f);
                    float x1 = fmaxf(dB[i][j][hh * 2 + 1] + b3s[c + 1], 0.f);
                    sts_hilo(smc + SM_A2H + row * STR + c * 2,
                             smc + SM_A2L + row * STR + c * 2, x0, x1);
                }
            }
        W_WAIT();
        __syncthreads();                   // A2 visible + W4 chunk ready
        gemm32x64(smc, SM_A2H, SM_A2L, SM_WH, SM_WL, R0, C0, g, t, dC);
        __syncthreads();                   // W4 chunk free
        if (nc < 3) {
            stage_w_async(smc, SM_WH, SM_WL,
                          g_w3t_h + (nc + 1) * 128 * DD, g_w3t_l + (nc + 1) * 128 * DD, 128);
            W_WAIT();
            __syncthreads();
        }
    }

    // ---- final epilogue: LN2(D2 + b4 + h1) -> out ----
    {
        const float* b4s = (const float*)(smc + SM_B4);
        float rs[2][2], rq[2][2];
#pragma unroll
        for (int i = 0; i < 2; i++)
#pragma unroll
            for (int hh = 0; hh < 2; hh++) {
                int row = R0 + i * 16 + hh * 8 + g;
                float s = 0.f, q = 0.f;
#pragma unroll
                for (int j = 0; j < 8; j++) {
                    int c = C0 + j * 8 + t * 2;
                    const char* pH = smc + SM_A1H + row * STR + c * 2;
                    const char* pL = smc + SM_A1L + row * STR + c * 2;
                    __nv_bfloat162 hh2 = *(const __nv_bfloat162*)(pH);
                    __nv_bfloat162 ll2 = *(const __nv_bfloat162*)(pL);
                    float x0 = dC[i][j][hh * 2] + b4s[c]
                             + __bfloat162float(hh2.x) + __bfloat162float(ll2.x);
                    float x1 = dC[i][j][hh * 2 + 1] + b4s[c + 1]
                             + __bfloat162float(hh2.y) + __bfloat162float(ll2.y);
                    dC[i][j][hh * 2] = x0;
                    dC[i][j][hh * 2 + 1] = x1;
                    s += x0 + x1;
                    q += x0 * x0 + x1 * x1;
                }
                rs[i][hh] = s; rq[i][hh] = q;
            }
#pragma unroll
        for (int i = 0; i < 2; i++)
#pragma unroll
            for (int hh = 0; hh < 2; hh++) {
                rs[i][hh] += __shfl_xor_sync(~0u, rs[i][hh], 1);
                rs[i][hh] += __shfl_xor_sync(~0u, rs[i][hh], 2);
                rq[i][hh] += __shfl_xor_sync(~0u, rq[i][hh], 1);
                rq[i][hh] += __shfl_xor_sync(~0u, rq[i][hh], 2);
            }
        if (t == 0) {
#pragma unroll
            for (int i = 0; i < 2; i++)
#pragma unroll
                for (int hh = 0; hh < 2; hh++) {
                    int row = R0 + i * 16 + hh * 8 + g;
                    sums[ng * 128 + row] = rs[i][hh];
                    sqs[ng * 128 + row] = rq[i][hh];
                }
        }
        __syncthreads();
        const float* g2s = (const float*)(smc + SM_G2);
        const float* be2s = (const float*)(smc + SM_BE2);
#pragma unroll
        for (int i = 0; i < 2; i++)
#pragma unroll
            for (int hh = 0; hh < 2; hh++) {
                int row = R0 + i * 16 + hh * 8 + g;
                int grow = row0 + row;
                float ts = sums[row] + sums[128 + row];
                float tq = sqs[row] + sqs[128 + row];
                float mu = ts * (1.f / 128.f);
                float inv = rsqrtf(fmaxf(tq * (1.f / 128.f) - mu * mu, 0.f) + 1e-5f);
                if (grow < NN) {
#pragma unroll
                    for (int j = 0; j < 8; j++) {
                        int c = C0 + j * 8 + t * 2;
                        float2 o;
                        o.x = (dC[i][j][hh * 2] - mu) * inv * g2s[c] + be2s[c];
                        o.y = (dC[i][j][hh * 2 + 1] - mu) * inv * g2s[c + 1] + be2s[c + 1];
                        *(float2*)&out[grow * DD + c] = o;
                    }
                }
            }
    }
}

// ---------------- launch ----------------
extern "C" void kernel_launch(void* const* d_in, const int* in_sizes, int n_in,
                              void* d_out, int out_size) {
    const float* h   = (const float*)d_in[0];
    const int*   src = (const int*)d_in[1];
    const int*   dst = (const int*)d_in[2];
    const float* W1  = (const float*)d_in[3];
    const float* b1  = (const float*)d_in[4];
    const float* W2  = (const float*)d_in[5];
    const float* b2  = (const float*)d_in[6];
    const float* W3  = (const float*)d_in[7];
    const float* b3  = (const float*)d_in[8];
    const float* W4  = (const float*)d_in[9];
    const float* b4  = (const float*)d_in[10];
    const float* g1  = (const float*)d_in[11];
    const float* be1 = (const float*)d_in[12];
    const float* g2  = (const float*)d_in[13];
    const float* be2 = (const float*)d_in[14];
    float* out = (float*)d_out;

    cudaFuncSetAttribute(k_gemm1_mma, cudaFuncAttributeMaxDynamicSharedMemorySize, SM1_TOTAL);
    cudaFuncSetAttribute(k_fused_mma, cudaFuncAttributeMaxDynamicSharedMemorySize, SM_TOTAL);

    k_zero<<<256, 256>>>();
    k_wconv_t<<<160, 256>>>(W1, W2, W3, W4);
    k_deg<<<(NE + 255) / 256, 256>>>(src, dst);
    k_scan_p1<<<NB_HE + NB_NODE, 1024>>>();
    k_scan_p2p3<<<NB_HE + NB_NODE, 1024>>>();
    k_place<<<(NE + 255) / 256, 256>>>(src, dst);
    k_gather1<<<(NH * 32 + 255) / 256, 256>>>(h);
    k_gemm1_mma<<<(NH + 127) / 128, 256, SM1_TOTAL>>>(b1);
    k_gather2<<<(NN * 32 + 255) / 256, 256>>>();
    k_fused_mma<<<(NN + 127) / 128, 256, SM_TOTAL>>>(h, b2, b3, b4,
                                                     g1, be1, g2, be2, out);
}